// round 4
// baseline (speedup 1.0000x reference)
#include <cuda_runtime.h>

// ---------------------------------------------------------------------------
// MultiheadChannelAttention — R3: free out_conv register budget (spill fix),
// pixel-pair FFMA2 packing in the depthwise conv. All fp32 numerics.
// ---------------------------------------------------------------------------

namespace {
constexpr int B = 8, C = 128, H = 128, W = 128;
constexpr int HW = H * W;      // 16384
constexpr int NH = 8;
constexpr int D = HW / NH;     // 2048
constexpr float SCALE = 1.0f / 128.0f;  // 1/sqrt(H*W)
}

typedef unsigned long long u64;

// packed fp32x2 helpers (ptxas never emits FFMA2 from C++ — PTX only)
__device__ __forceinline__ void ffma2(u64& d, u64 a, u64 b) {
    asm("fma.rn.f32x2 %0, %1, %2, %0;" : "+l"(d) : "l"(a), "l"(b));
}
__device__ __forceinline__ u64 bcast2(float f) {
    u64 r;
    asm("mov.b64 %0, {%1, %1};" : "=l"(r) : "f"(f));
    return r;
}
__device__ __forceinline__ u64 pack2(float lo, float hi) {
    u64 r;
    asm("mov.b64 %0, {%1, %2};" : "=l"(r) : "f"(lo), "f"(hi));
    return r;
}
__device__ __forceinline__ float2 unpack2(u64 v) {
    float2 r;
    asm("mov.b64 {%0, %1}, %2;" : "=f"(r.x), "=f"(r.y) : "l"(v));
    return r;
}

// Scratch (device globals: no allocation allowed)
__device__ float g_q[B * C * HW];
__device__ float g_k[B * C * HW];
__device__ float g_v[B * C * HW];
__device__ float g_s[B * NH * C * C];   // scores -> softmax probs (in place)
__device__ float g_a[B * C * HW];       // attention output (pre out-conv)
__device__ float g_wt[C * 9 * C];       // wo transposed to [ci][tap][co]

// ---------------------------------------------------------------------------
// Transpose wo [co][ci][tap] -> g_wt [ci][tap][co]
// ---------------------------------------------------------------------------
__global__ void wt_transpose(const float* __restrict__ wo) {
    int i = blockIdx.x * 256 + threadIdx.x;
    if (i >= C * C * 9) return;
    int co = i / (C * 9);
    int rem = i % (C * 9);
    int ci = rem / 9;
    int tap = rem % 9;
    g_wt[(ci * 9 + tap) * C + co] = wo[i];
}

// ---------------------------------------------------------------------------
// Fused q/k/v depthwise 9x9 conv (pad 4). Block tile = 64x32 of one (b,c)
// plane; thread = 8 adjacent x-pixels (4 f32x2 pairs), window row in regs.
// grid (W/64, H/32, B*C), 256 threads.
// ---------------------------------------------------------------------------
__global__ void __launch_bounds__(256) qkv_dwconv(
        const float* __restrict__ x,
        const float* __restrict__ wq, const float* __restrict__ bq,
        const float* __restrict__ wk, const float* __restrict__ bk,
        const float* __restrict__ wv, const float* __restrict__ bv) {
    __shared__ float tile[40][72];
    __shared__ float wsm[3][81];

    int bc = blockIdx.z;
    int b = bc >> 7, c = bc & 127;
    int x0 = blockIdx.x * 64, y0 = blockIdx.y * 32;
    int tid = threadIdx.x;
    int lane = tid & 7;      // 8-pixel group: x = x0 + lane*8 + p
    int r = tid >> 3;        // output row 0..31

    if (tid < 243) {
        int c3 = tid / 81, t = tid % 81;
        const float* wsrc = (c3 == 0) ? wq : (c3 == 1) ? wk : wv;
        wsm[c3][t] = wsrc[c * 81 + t];
    }
    const float* xp = x + (size_t)(b * C + c) * HW;
    for (int i = tid; i < 40 * 72; i += 256) {
        int tr = i / 72, tc = i % 72;
        int gy = y0 - 4 + tr, gx = x0 - 4 + tc;
        float v = 0.0f;
        if ((unsigned)gy < (unsigned)H && (unsigned)gx < (unsigned)W)
            v = xp[gy * W + gx];
        tile[tr][tc] = v;
    }
    __syncthreads();

    // accumulators: 4 pixel-pairs per conv
    u64 aq[4], ak[4], av[4];
    float biasq = bq[c], biask = bk[c], biasv = bv[c];
#pragma unroll
    for (int p = 0; p < 4; p++) {
        aq[p] = bcast2(biasq);
        ak[p] = bcast2(biask);
        av[p] = bcast2(biasv);
    }

#pragma unroll
    for (int ky = 0; ky < 9; ky++) {
        float win[16];
        float4 u0 = *(const float4*)&tile[r + ky][lane * 8];
        float4 u1 = *(const float4*)&tile[r + ky][lane * 8 + 4];
        float4 u2 = *(const float4*)&tile[r + ky][lane * 8 + 8];
        float4 u3 = *(const float4*)&tile[r + ky][lane * 8 + 12];
        win[0] = u0.x; win[1] = u0.y; win[2] = u0.z; win[3] = u0.w;
        win[4] = u1.x; win[5] = u1.y; win[6] = u1.z; win[7] = u1.w;
        win[8] = u2.x; win[9] = u2.y; win[10] = u2.z; win[11] = u2.w;
        win[12] = u3.x; win[13] = u3.y; win[14] = u3.z; win[15] = u3.w;

        // all consecutive pairs {win[j], win[j+1]}, j=0..14, shared by q/k/v
        u64 wp[15];
#pragma unroll
        for (int j = 0; j < 15; j++)
            wp[j] = pack2(win[j], win[j + 1]);

#pragma unroll
        for (int kx = 0; kx < 9; kx++) {
            u64 w0 = bcast2(wsm[0][ky * 9 + kx]);
            u64 w1 = bcast2(wsm[1][ky * 9 + kx]);
            u64 w2 = bcast2(wsm[2][ky * 9 + kx]);
#pragma unroll
            for (int p = 0; p < 4; p++) {
                u64 vi = wp[2 * p + kx];
                ffma2(aq[p], vi, w0);
                ffma2(ak[p], vi, w1);
                ffma2(av[p], vi, w2);
            }
        }
    }

    size_t o = (size_t)(b * C + c) * HW + (size_t)(y0 + r) * W + x0 + lane * 8;
    float2 q0 = unpack2(aq[0]), q1 = unpack2(aq[1]), q2 = unpack2(aq[2]), q3 = unpack2(aq[3]);
    float2 k0 = unpack2(ak[0]), k1 = unpack2(ak[1]), k2 = unpack2(ak[2]), k3 = unpack2(ak[3]);
    float2 v0 = unpack2(av[0]), v1 = unpack2(av[1]), v2 = unpack2(av[2]), v3 = unpack2(av[3]);
    *(float4*)&g_q[o]     = make_float4(q0.x, q0.y, q1.x, q1.y);
    *(float4*)&g_q[o + 4] = make_float4(q2.x, q2.y, q3.x, q3.y);
    *(float4*)&g_k[o]     = make_float4(k0.x, k0.y, k1.x, k1.y);
    *(float4*)&g_k[o + 4] = make_float4(k2.x, k2.y, k3.x, k3.y);
    *(float4*)&g_v[o]     = make_float4(v0.x, v0.y, v1.x, v1.y);
    *(float4*)&g_v[o + 4] = make_float4(v2.x, v2.y, v3.x, v3.y);
}

// ---------------------------------------------------------------------------
// S = (Q K^T) * SCALE per (b,h). Block = 64 rows x 128 cols, K=2048.
// grid (2, B*NH) = 128 blocks. Thread = 4 rows x 8 cols (f32x2 pairs on cols).
// ---------------------------------------------------------------------------
__global__ void __launch_bounds__(256) score_gemm() {
    __shared__ float Qs[32][68];
    __shared__ float Ks[32][132];

    int bh = blockIdx.y;
    int b = bh >> 3, h = bh & 7;
    int r0 = blockIdx.x * 64;
    int tx = threadIdx.x, ty = threadIdx.y;
    int tid = ty * 16 + tx;

    const float* qb = g_q + (size_t)(b * C) * HW + h * D;
    const float* kb = g_k + (size_t)(b * C) * HW + h * D;

    u64 acc[4][4] = {};

    for (int kt = 0; kt < D; kt += 32) {
#pragma unroll
        for (int l = 0; l < 8; l++) {
            int i = tid + 256 * l;
            int r = i >> 5, j = i & 31;
            Qs[j][r] = qb[(size_t)(r0 + r) * HW + kt + j];
            int col = i >> 5, j2 = i & 31;
            Ks[j2][col * 2] = kb[(size_t)(col * 2) * HW + kt + j2];
            Ks[j2][col * 2 + 1] = kb[(size_t)(col * 2 + 1) * HW + kt + j2];
        }
        __syncthreads();
#pragma unroll
        for (int kk = 0; kk < 32; kk++) {
            float4 a = *(const float4*)&Qs[kk][ty * 4];
            u64 ap[4] = {bcast2(a.x), bcast2(a.y), bcast2(a.z), bcast2(a.w)};
            u64 bp[4];
#pragma unroll
            for (int j = 0; j < 4; j++)
                bp[j] = *(const u64*)&Ks[kk][tx * 8 + 2 * j];
#pragma unroll
            for (int ii = 0; ii < 4; ii++)
#pragma unroll
                for (int jj = 0; jj < 4; jj++)
                    ffma2(acc[ii][jj], ap[ii], bp[jj]);
        }
        __syncthreads();
    }

#pragma unroll
    for (int ii = 0; ii < 4; ii++) {
        int rr = r0 + ty * 4 + ii;
        float2 p0 = unpack2(acc[ii][0]);
        float2 p1 = unpack2(acc[ii][1]);
        float2 p2 = unpack2(acc[ii][2]);
        float2 p3 = unpack2(acc[ii][3]);
        float4 o0 = make_float4(p0.x * SCALE, p0.y * SCALE, p1.x * SCALE, p1.y * SCALE);
        float4 o1 = make_float4(p2.x * SCALE, p2.y * SCALE, p3.x * SCALE, p3.y * SCALE);
        *(float4*)&g_s[((size_t)bh * C + rr) * C + tx * 8] = o0;
        *(float4*)&g_s[((size_t)bh * C + rr) * C + tx * 8 + 4] = o1;
    }
}

// ---------------------------------------------------------------------------
// Row softmax over g_s (8192 rows of 128), fp32, in place. One warp per row.
// ---------------------------------------------------------------------------
__global__ void softmax_rows() {
    int gw = (blockIdx.x * blockDim.x + threadIdx.x) >> 5;
    int lane = threadIdx.x & 31;
    if (gw >= B * NH * C) return;
    float4 v = *(const float4*)&g_s[(size_t)gw * C + lane * 4];
    float m = fmaxf(fmaxf(v.x, v.y), fmaxf(v.z, v.w));
#pragma unroll
    for (int o = 16; o > 0; o >>= 1)
        m = fmaxf(m, __shfl_xor_sync(0xffffffffu, m, o));
    v.x = __expf(v.x - m);
    v.y = __expf(v.y - m);
    v.z = __expf(v.z - m);
    v.w = __expf(v.w - m);
    float s = v.x + v.y + v.z + v.w;
#pragma unroll
    for (int o = 16; o > 0; o >>= 1)
        s += __shfl_xor_sync(0xffffffffu, s, o);
    float inv = 1.0f / s;
    v.x *= inv; v.y *= inv; v.z *= inv; v.w *= inv;
    *(float4*)&g_s[(size_t)gw * C + lane * 4] = v;
}

// ---------------------------------------------------------------------------
// A = P V per (b,h): block = 128 c-rows x 128 d-cols, K=128 in chunks of 32.
// Thread = 8 rows x 8 cols (f32x2 pairs on cols). grid (16, B*NH).
// ---------------------------------------------------------------------------
__global__ void __launch_bounds__(256) pv_gemm() {
    __shared__ float Ps[32][132];
    __shared__ float Vs[32][132];

    int bh = blockIdx.y;
    int b = bh >> 3, h = bh & 7;
    int dt = blockIdx.x * 128;
    int tx = threadIdx.x, ty = threadIdx.y;
    int tid = ty * 16 + tx;

    const float* pb = g_s + (size_t)bh * C * C;
    const float* vb = g_v + (size_t)(b * C) * HW + h * D + dt;

    u64 acc[8][4] = {};

    for (int et = 0; et < C; et += 32) {
#pragma unroll
        for (int l = 0; l < 16; l++) {
            int i = tid + 256 * l;
            int r = i >> 5, e = i & 31;            // P: 128 rows x 32 e
            Ps[e][r] = pb[(size_t)r * C + et + e];
            int e2 = i >> 7, dc = i & 127;         // V: 32 e x 128 d
            Vs[e2][dc] = vb[(size_t)(et + e2) * HW + dc];
        }
        __syncthreads();
#pragma unroll
        for (int kk = 0; kk < 32; kk++) {
            float4 a0 = *(const float4*)&Ps[kk][ty * 8];
            float4 a1 = *(const float4*)&Ps[kk][ty * 8 + 4];
            u64 ap[8] = {bcast2(a0.x), bcast2(a0.y), bcast2(a0.z), bcast2(a0.w),
                         bcast2(a1.x), bcast2(a1.y), bcast2(a1.z), bcast2(a1.w)};
            u64 bp[4];
#pragma unroll
            for (int j = 0; j < 4; j++)
                bp[j] = *(const u64*)&Vs[kk][tx * 8 + 2 * j];
#pragma unroll
            for (int ii = 0; ii < 8; ii++)
#pragma unroll
                for (int jj = 0; jj < 4; jj++)
                    ffma2(acc[ii][jj], ap[ii], bp[jj]);
        }
        __syncthreads();
    }

    float* ab = g_a + (size_t)(b * C) * HW + h * D + dt;
#pragma unroll
    for (int ii = 0; ii < 8; ii++) {
        int r = ty * 8 + ii;
        float2 p0 = unpack2(acc[ii][0]);
        float2 p1 = unpack2(acc[ii][1]);
        float2 p2 = unpack2(acc[ii][2]);
        float2 p3 = unpack2(acc[ii][3]);
        *(float4*)&ab[(size_t)r * HW + tx * 8]     = make_float4(p0.x, p0.y, p1.x, p1.y);
        *(float4*)&ab[(size_t)r * HW + tx * 8 + 4] = make_float4(p2.x, p2.y, p3.x, p3.y);
    }
}

// ---------------------------------------------------------------------------
// Dense 3x3 conv (pad 1), 128->128 + bias, FFMA2 packed along co pairs.
// Block = one output row y of one batch (128 co x 128 x); ci chunks of 4.
// Thread = 8 co (4 pairs) x 8 x. grid (H, B).
// NOTE: no min-blocks clause — let ptxas use >128 regs (spill fix).
// ---------------------------------------------------------------------------
__global__ void __launch_bounds__(256) out_conv(const float* __restrict__ bo,
                                                float* __restrict__ out) {
    __shared__ float in_s[4][3][132];   // [ci][y-1..y+1][x=-1..128]
    __shared__ float w_s[4][9][128];    // [ci][tap][co]

    int y = blockIdx.x;
    int b = blockIdx.y;
    int tid = threadIdx.x;
    int tx = tid & 15;    // pixel group: x = tx*8 + p
    int ty = tid >> 4;    // co group: co = ty*8 + i

    u64 acc[4][8] = {};   // [co-pair][pixel]

    for (int ci0 = 0; ci0 < C; ci0 += 4) {
        for (int i = tid; i < 4 * 3 * 130; i += 256) {
            int ci = i / 390;
            int rem = i % 390;
            int ry = rem / 130;
            int cc = rem % 130;
            int gy = y + ry - 1;
            int gx = cc - 1;
            float v = 0.0f;
            if ((unsigned)gy < (unsigned)H && (unsigned)gx < (unsigned)W)
                v = g_a[(size_t)(b * C + ci0 + ci) * HW + gy * W + gx];
            in_s[ci][ry][cc] = v;
        }
        for (int i = tid; i < 4 * 9 * 128; i += 256)
            ((float*)w_s)[i] = g_wt[ci0 * (9 * C) + i];
        __syncthreads();

#pragma unroll
        for (int ci = 0; ci < 4; ci++) {
#pragma unroll
            for (int dy = 0; dy < 3; dy++) {
                u64 winb[10];
#pragma unroll
                for (int j = 0; j < 10; j++)
                    winb[j] = bcast2(in_s[ci][dy][tx * 8 + j]);
#pragma unroll
                for (int dx = 0; dx < 3; dx++) {
#pragma unroll
                    for (int i4 = 0; i4 < 4; i4++) {
                        u64 wp = *(const u64*)&w_s[ci][dy * 3 + dx][ty * 8 + i4 * 2];
#pragma unroll
                        for (int p = 0; p < 8; p++)
                            ffma2(acc[i4][p], wp, winb[p + dx]);
                    }
                }
            }
        }
        __syncthreads();
    }

#pragma unroll
    for (int i4 = 0; i4 < 4; i4++) {
        float lo[8], hi[8];
#pragma unroll
        for (int p = 0; p < 8; p++) {
            float2 u = unpack2(acc[i4][p]);
            lo[p] = u.x; hi[p] = u.y;
        }
        int co0 = ty * 8 + i4 * 2;
        float b0 = bo[co0], b1 = bo[co0 + 1];
        size_t base0 = (size_t)(b * C + co0) * HW + (size_t)y * W + tx * 8;
        size_t base1 = base0 + HW;
        *(float4*)&out[base0]     = make_float4(lo[0] + b0, lo[1] + b0, lo[2] + b0, lo[3] + b0);
        *(float4*)&out[base0 + 4] = make_float4(lo[4] + b0, lo[5] + b0, lo[6] + b0, lo[7] + b0);
        *(float4*)&out[base1]     = make_float4(hi[0] + b1, hi[1] + b1, hi[2] + b1, hi[3] + b1);
        *(float4*)&out[base1 + 4] = make_float4(hi[4] + b1, hi[5] + b1, hi[6] + b1, hi[7] + b1);
    }
}

// ---------------------------------------------------------------------------
extern "C" void kernel_launch(void* const* d_in, const int* in_sizes, int n_in,
                              void* d_out, int out_size) {
    const float* x  = (const float*)d_in[0];
    const float* wq = (const float*)d_in[1];
    const float* bq = (const float*)d_in[2];
    const float* wk = (const float*)d_in[3];
    const float* bk = (const float*)d_in[4];
    const float* wv = (const float*)d_in[5];
    const float* bv = (const float*)d_in[6];
    const float* wo = (const float*)d_in[7];
    const float* bo = (const float*)d_in[8];
    float* out = (float*)d_out;

    wt_transpose<<<(C * C * 9 + 255) / 256, 256>>>(wo);
    qkv_dwconv<<<dim3(W / 64, H / 32, B * C), 256>>>(x, wq, bq, wk, bk, wv, bv);
    score_gemm<<<dim3(2, B * NH), dim3(16, 16)>>>();
    softmax_rows<<<(B * NH * C) / 8, 256>>>();
    pv_gemm<<<dim3(HW / NH / 128, B * NH), dim3(16, 16)>>>();
    out_conv<<<dim3(H, B), 256>>>(bo, out);
}

// round 10
// speedup vs baseline: 1.5598x; 1.5598x over previous
#include <cuda_runtime.h>
#include <cuda_bf16.h>
#include <cstdint>

// ---------------------------------------------------------------------------
// MultiheadChannelAttention — R9: out_conv via mma.sync bf16 (m16n8k16,
// baseline PTX — harness targets sm_103 WITHOUT 'a', so no tcgen05).
// bf16 2-way split (3 MMA terms) keeps rel_err ~1e-5.
// ---------------------------------------------------------------------------

namespace {
constexpr int B = 8, C = 128, H = 128, W = 128;
constexpr int HW = H * W;      // 16384
constexpr int NH = 8;
constexpr int D = HW / NH;     // 2048
constexpr float SCALE = 1.0f / 128.0f;

// out_conv smem: 4 tiles of 128 rows x 136 bf16 (128 + 8 pad), 272 B rows
constexpr int LDT_B = 272;                  // row stride bytes
constexpr int TILE_B2 = 128 * LDT_B;        // 34816 per tile
constexpr int SA_H = 0;
constexpr int SA_L = SA_H + TILE_B2;
constexpr int SB_H = SA_L + TILE_B2;
constexpr int SB_L = SB_H + TILE_B2;
constexpr int SMEM_TOTAL = SB_L + TILE_B2;  // 139264 B
}

typedef unsigned long long u64;

// Scratch (device globals: no allocation allowed)
__device__ float g_q[B * C * HW];
__device__ float g_k[B * C * HW];
__device__ float g_v[B * C * HW];
__device__ float g_s[B * NH * C * C];
__device__ __nv_bfloat16 g_ah[(size_t)B * HW * C];  // attention out, hi split, [b][pix][ci]
__device__ __nv_bfloat16 g_al[(size_t)B * HW * C];  // lo split
__device__ __nv_bfloat16 g_wh[9 * C * C];           // wo hi split, [tap][co][ci]
__device__ __nv_bfloat16 g_wl[9 * C * C];

// ---------------- helpers ---------------------------------------------------
__device__ __forceinline__ uint32_t smem_u32(const void* p) {
    uint32_t a;
    asm("{ .reg .u64 t; cvta.to.shared.u64 t, %1; cvt.u32.u64 %0, t; }" : "=r"(a) : "l"(p));
    return a;
}
__device__ __forceinline__ void ffma2(u64& d, u64 a, u64 b) {
    asm("fma.rn.f32x2 %0, %1, %2, %0;" : "+l"(d) : "l"(a), "l"(b));
}
__device__ __forceinline__ u64 bcast2(float f) {
    u64 r;
    asm("mov.b64 %0, {%1, %1};" : "=l"(r) : "f"(f));
    return r;
}
__device__ __forceinline__ float2 unpack2(u64 v) {
    float2 r;
    asm("mov.b64 {%0, %1}, %2;" : "=f"(r.x), "=f"(r.y) : "l"(v));
    return r;
}

#define LDSM4(r, addr)                                                          \
    asm volatile("ldmatrix.sync.aligned.m8n8.x4.shared.b16 {%0,%1,%2,%3}, [%4];" \
        : "=r"((r)[0]), "=r"((r)[1]), "=r"((r)[2]), "=r"((r)[3]) : "r"(addr))

#define MMA_BF16(d, a, b0, b1)                                                  \
    asm volatile("mma.sync.aligned.m16n8k16.row.col.f32.bf16.bf16.f32 "         \
        "{%0,%1,%2,%3}, {%4,%5,%6,%7}, {%8,%9}, {%0,%1,%2,%3};"                 \
        : "+f"((d)[0]), "+f"((d)[1]), "+f"((d)[2]), "+f"((d)[3])                \
        : "r"((a)[0]), "r"((a)[1]), "r"((a)[2]), "r"((a)[3]), "r"(b0), "r"(b1))

union Pack8 { uint4 u; __nv_bfloat16 h[8]; };

// ---------------------------------------------------------------------------
// Split wo [co][ci][tap] -> g_wh/g_wl [tap][co][ci] (bf16 hi/lo)
// ---------------------------------------------------------------------------
__global__ void prep_w(const float* __restrict__ wo) {
    int i = blockIdx.x * 256 + threadIdx.x;
    if (i >= C * C * 9) return;
    int co = i / (C * 9);
    int rem = i % (C * 9);
    int ci = rem / 9;
    int tap = rem % 9;
    float w = wo[i];
    __nv_bfloat16 hi = __float2bfloat16(w);
    __nv_bfloat16 lo = __float2bfloat16(w - __bfloat162float(hi));
    int dst = tap * (C * C) + co * C + ci;
    g_wh[dst] = hi;
    g_wl[dst] = lo;
}

// ---------------------------------------------------------------------------
// Fused q/k/v depthwise 9x9 conv (pad 4) — proven R2 float version.
// ---------------------------------------------------------------------------
__global__ void __launch_bounds__(256) qkv_dwconv(
        const float* __restrict__ x,
        const float* __restrict__ wq, const float* __restrict__ bq,
        const float* __restrict__ wk, const float* __restrict__ bk,
        const float* __restrict__ wv, const float* __restrict__ bv) {
    __shared__ float tile[40][72];
    __shared__ float wsm[3][81];

    int bc = blockIdx.z;
    int b = bc >> 7, c = bc & 127;
    int x0 = blockIdx.x * 64, y0 = blockIdx.y * 32;
    int tid = threadIdx.x;
    int lane = tid & 7;
    int r = tid >> 3;

    if (tid < 243) {
        int c3 = tid / 81, t = tid % 81;
        const float* wsrc = (c3 == 0) ? wq : (c3 == 1) ? wk : wv;
        wsm[c3][t] = wsrc[c * 81 + t];
    }
    const float* xp = x + (size_t)(b * C + c) * HW;
    for (int i = tid; i < 40 * 72; i += 256) {
        int tr = i / 72, tc = i % 72;
        int gy = y0 - 4 + tr, gx = x0 - 4 + tc;
        float v = 0.0f;
        if ((unsigned)gy < (unsigned)H && (unsigned)gx < (unsigned)W)
            v = xp[gy * W + gx];
        tile[tr][tc] = v;
    }
    __syncthreads();

    float aq[8], ak[8], av[8];
    float biasq = bq[c], biask = bk[c], biasv = bv[c];
#pragma unroll
    for (int p = 0; p < 8; p++) { aq[p] = biasq; ak[p] = biask; av[p] = biasv; }

#pragma unroll
    for (int ky = 0; ky < 9; ky++) {
        float win[16];
        float4 u0 = *(const float4*)&tile[r + ky][lane * 8];
        float4 u1 = *(const float4*)&tile[r + ky][lane * 8 + 4];
        float4 u2 = *(const float4*)&tile[r + ky][lane * 8 + 8];
        float4 u3 = *(const float4*)&tile[r + ky][lane * 8 + 12];
        win[0] = u0.x; win[1] = u0.y; win[2] = u0.z; win[3] = u0.w;
        win[4] = u1.x; win[5] = u1.y; win[6] = u1.z; win[7] = u1.w;
        win[8] = u2.x; win[9] = u2.y; win[10] = u2.z; win[11] = u2.w;
        win[12] = u3.x; win[13] = u3.y; win[14] = u3.z; win[15] = u3.w;
#pragma unroll
        for (int kx = 0; kx < 9; kx++) {
            float w0 = wsm[0][ky * 9 + kx];
            float w1 = wsm[1][ky * 9 + kx];
            float w2 = wsm[2][ky * 9 + kx];
#pragma unroll
            for (int p = 0; p < 8; p++) {
                float vi = win[p + kx];
                aq[p] += vi * w0;
                ak[p] += vi * w1;
                av[p] += vi * w2;
            }
        }
    }

    size_t o = (size_t)(b * C + c) * HW + (size_t)(y0 + r) * W + x0 + lane * 8;
    *(float4*)&g_q[o]     = make_float4(aq[0], aq[1], aq[2], aq[3]);
    *(float4*)&g_q[o + 4] = make_float4(aq[4], aq[5], aq[6], aq[7]);
    *(float4*)&g_k[o]     = make_float4(ak[0], ak[1], ak[2], ak[3]);
    *(float4*)&g_k[o + 4] = make_float4(ak[4], ak[5], ak[6], ak[7]);
    *(float4*)&g_v[o]     = make_float4(av[0], av[1], av[2], av[3]);
    *(float4*)&g_v[o + 4] = make_float4(av[4], av[5], av[6], av[7]);
}

// ---------------------------------------------------------------------------
// S = (Q K^T) * SCALE per (b,h). (unchanged, passed R3)
// ---------------------------------------------------------------------------
__global__ void __launch_bounds__(256) score_gemm() {
    __shared__ float Qs[32][68];
    __shared__ float Ks[32][132];

    int bh = blockIdx.y;
    int b = bh >> 3, h = bh & 7;
    int r0 = blockIdx.x * 64;
    int tx = threadIdx.x, ty = threadIdx.y;
    int tid = ty * 16 + tx;

    const float* qb = g_q + (size_t)(b * C) * HW + h * D;
    const float* kb = g_k + (size_t)(b * C) * HW + h * D;

    u64 acc[4][4] = {};

    for (int kt = 0; kt < D; kt += 32) {
#pragma unroll
        for (int l = 0; l < 8; l++) {
            int i = tid + 256 * l;
            int r = i >> 5, j = i & 31;
            Qs[j][r] = qb[(size_t)(r0 + r) * HW + kt + j];
            int col = i >> 5, j2 = i & 31;
            Ks[j2][col * 2] = kb[(size_t)(col * 2) * HW + kt + j2];
            Ks[j2][col * 2 + 1] = kb[(size_t)(col * 2 + 1) * HW + kt + j2];
        }
        __syncthreads();
#pragma unroll
        for (int kk = 0; kk < 32; kk++) {
            float4 a = *(const float4*)&Qs[kk][ty * 4];
            u64 ap[4] = {bcast2(a.x), bcast2(a.y), bcast2(a.z), bcast2(a.w)};
            u64 bp[4];
#pragma unroll
            for (int j = 0; j < 4; j++)
                bp[j] = *(const u64*)&Ks[kk][tx * 8 + 2 * j];
#pragma unroll
            for (int ii = 0; ii < 4; ii++)
#pragma unroll
                for (int jj = 0; jj < 4; jj++)
                    ffma2(acc[ii][jj], ap[ii], bp[jj]);
        }
        __syncthreads();
    }

#pragma unroll
    for (int ii = 0; ii < 4; ii++) {
        int rr = r0 + ty * 4 + ii;
        float2 p0 = unpack2(acc[ii][0]);
        float2 p1 = unpack2(acc[ii][1]);
        float2 p2 = unpack2(acc[ii][2]);
        float2 p3 = unpack2(acc[ii][3]);
        float4 o0 = make_float4(p0.x * SCALE, p0.y * SCALE, p1.x * SCALE, p1.y * SCALE);
        float4 o1 = make_float4(p2.x * SCALE, p2.y * SCALE, p3.x * SCALE, p3.y * SCALE);
        *(float4*)&g_s[((size_t)bh * C + rr) * C + tx * 8] = o0;
        *(float4*)&g_s[((size_t)bh * C + rr) * C + tx * 8 + 4] = o1;
    }
}

// ---------------------------------------------------------------------------
// Row softmax (unchanged)
// ---------------------------------------------------------------------------
__global__ void softmax_rows() {
    int gw = (blockIdx.x * blockDim.x + threadIdx.x) >> 5;
    int lane = threadIdx.x & 31;
    if (gw >= B * NH * C) return;
    float4 v = *(const float4*)&g_s[(size_t)gw * C + lane * 4];
    float m = fmaxf(fmaxf(v.x, v.y), fmaxf(v.z, v.w));
#pragma unroll
    for (int o = 16; o > 0; o >>= 1)
        m = fmaxf(m, __shfl_xor_sync(0xffffffffu, m, o));
    v.x = __expf(v.x - m);
    v.y = __expf(v.y - m);
    v.z = __expf(v.z - m);
    v.w = __expf(v.w - m);
    float s = v.x + v.y + v.z + v.w;
#pragma unroll
    for (int o = 16; o > 0; o >>= 1)
        s += __shfl_xor_sync(0xffffffffu, s, o);
    float inv = 1.0f / s;
    v.x *= inv; v.y *= inv; v.z *= inv; v.w *= inv;
    *(float4*)&g_s[(size_t)gw * C + lane * 4] = v;
}

// ---------------------------------------------------------------------------
// A = P V per (b,h); writes SPLIT bf16 output in pixel-major [b][pix][ci].
// ---------------------------------------------------------------------------
__global__ void __launch_bounds__(256) pv_gemm() {
    __shared__ float Ps[32][132];
    __shared__ float Vs[32][132];

    int bh = blockIdx.y;
    int b = bh >> 3, h = bh & 7;
    int dt = blockIdx.x * 128;
    int tx = threadIdx.x, ty = threadIdx.y;
    int tid = ty * 16 + tx;

    const float* pb = g_s + (size_t)bh * C * C;
    const float* vb = g_v + (size_t)(b * C) * HW + h * D + dt;

    u64 acc[8][4] = {};

    for (int et = 0; et < C; et += 32) {
#pragma unroll
        for (int l = 0; l < 16; l++) {
            int i = tid + 256 * l;
            int r = i >> 5, e = i & 31;
            Ps[e][r] = pb[(size_t)r * C + et + e];
            int e2 = i >> 7, dc = i & 127;
            Vs[e2][dc] = vb[(size_t)(et + e2) * HW + dc];
        }
        __syncthreads();
#pragma unroll
        for (int kk = 0; kk < 32; kk++) {
            float4 a0 = *(const float4*)&Ps[kk][ty * 8];
            float4 a1 = *(const float4*)&Ps[kk][ty * 8 + 4];
            u64 ap[8] = {bcast2(a0.x), bcast2(a0.y), bcast2(a0.z), bcast2(a0.w),
                         bcast2(a1.x), bcast2(a1.y), bcast2(a1.z), bcast2(a1.w)};
            u64 bp[4];
#pragma unroll
            for (int j = 0; j < 4; j++)
                bp[j] = *(const u64*)&Vs[kk][tx * 8 + 2 * j];
#pragma unroll
            for (int ii = 0; ii < 8; ii++)
#pragma unroll
                for (int jj = 0; jj < 4; jj++)
                    ffma2(acc[ii][jj], ap[ii], bp[jj]);
        }
        __syncthreads();
    }

    float a_f[8][8];
#pragma unroll
    for (int ii = 0; ii < 8; ii++) {
#pragma unroll
        for (int jj = 0; jj < 4; jj++) {
            float2 p = unpack2(acc[ii][jj]);
            a_f[ii][2 * jj] = p.x;
            a_f[ii][2 * jj + 1] = p.y;
        }
    }
#pragma unroll
    for (int dd = 0; dd < 8; dd++) {
        Pack8 ph, pl;
#pragma unroll
        for (int ii = 0; ii < 8; ii++) {
            float a = a_f[ii][dd];
            __nv_bfloat16 hi = __float2bfloat16(a);
            ph.h[ii] = hi;
            pl.h[ii] = __float2bfloat16(a - __bfloat162float(hi));
        }
        size_t pix = (size_t)h * D + dt + tx * 8 + dd;
        size_t base = ((size_t)b * HW + pix) * C + ty * 8;
        *(uint4*)&g_ah[base] = ph.u;
        *(uint4*)&g_al[base] = pl.u;
    }
}

// ---------------------------------------------------------------------------
// out_conv via mma.sync bf16: per CTA (b,y): D[co=128][x=128] = sum over
// 9 taps of W_tap[co][ci] * act[pix(y+dy-1, x+dx-1)][ci], K=128 per tap.
// 3-term bf16 split. 8 warps = 4(M) x 2(N); warp tile 32co x 64x.
// grid (H, B), 256 threads.
// ---------------------------------------------------------------------------
__global__ void __launch_bounds__(256) out_conv_mma(const float* __restrict__ bo,
                                                    float* __restrict__ out) {
    extern __shared__ char smem[];
    uint32_t sb = smem_u32(smem);
    const int tid = threadIdx.x;
    const int wid = tid >> 5, lane = tid & 31;
    const int y = blockIdx.x, b = blockIdx.y;
    const int wm = wid & 3;      // M warp: 32 co
    const int wn = wid >> 2;     // N warp: 64 x

    float acc[2][8][4];
#pragma unroll
    for (int mt = 0; mt < 2; mt++)
#pragma unroll
        for (int nt = 0; nt < 8; nt++)
#pragma unroll
            for (int j = 0; j < 4; j++) acc[mt][nt][j] = 0.0f;

    const uint4* whp = (const uint4*)g_wh;
    const uint4* wlp = (const uint4*)g_wl;
    const uint4* ahp = (const uint4*)g_ah;
    const uint4* alp = (const uint4*)g_al;
    const uint4 z4 = make_uint4(0, 0, 0, 0);

    for (int tap = 0; tap < 9; tap++) {
        int dy = tap / 3, dx = tap % 3;
        int yy = y + dy - 1;
        bool yok = (unsigned)yy < (unsigned)H;

        // stage 4 tiles: Ah/Al = weights[tap][co][ci], Bh/Bl = act rows (x+dx-1)
#pragma unroll
        for (int l = 0; l < 8; l++) {
            int i = tid + 256 * l;            // 0..2047
            int row = i >> 4, cg = i & 15;    // row 0..127, 16B-group 0..15
            uint32_t off = (uint32_t)row * LDT_B + cg * 16;
            size_t widx = (size_t)tap * 2048 + row * 16 + cg;
            *(uint4*)(smem + SA_H + off) = whp[widx];
            *(uint4*)(smem + SA_L + off) = wlp[widx];
            int xx = row + dx - 1;
            uint4 vh = z4, vl = z4;
            if (yok && (unsigned)xx < (unsigned)W) {
                size_t aidx = ((size_t)b * HW + yy * W + xx) * 16 + cg;
                vh = ahp[aidx];
                vl = alp[aidx];
            }
            *(uint4*)(smem + SB_H + off) = vh;
            *(uint4*)(smem + SB_L + off) = vl;
        }
        __syncthreads();

#pragma unroll
        for (int ks = 0; ks < 8; ks++) {
            uint32_t ah[2][4], al[2][4], bh[4][4], bl[4][4];
#pragma unroll
            for (int mt = 0; mt < 2; mt++) {
                uint32_t addr = sb + SA_H
                    + (uint32_t)(wm * 32 + mt * 16 + (lane & 15)) * LDT_B
                    + (uint32_t)(ks * 16 + (lane >> 4) * 8) * 2;
                LDSM4(ah[mt], addr);
                LDSM4(al[mt], addr + (SA_L - SA_H));
            }
#pragma unroll
            for (int np = 0; np < 4; np++) {
                int n = wn * 64 + np * 16 + (lane & 7) + ((lane >> 4) & 1) * 8;
                int ko = ks * 16 + ((lane >> 3) & 1) * 8;
                uint32_t addr = sb + SB_H + (uint32_t)n * LDT_B + (uint32_t)ko * 2;
                LDSM4(bh[np], addr);
                LDSM4(bl[np], addr + (SB_L - SB_H));
            }
#pragma unroll
            for (int mt = 0; mt < 2; mt++) {
#pragma unroll
                for (int nt = 0; nt < 8; nt++) {
                    int np = nt >> 1, hf = (nt & 1) * 2;
                    MMA_BF16(acc[mt][nt], ah[mt], bh[np][hf], bh[np][hf + 1]);
                    MMA_BF16(acc[mt][nt], ah[mt], bl[np][hf], bl[np][hf + 1]);
                    MMA_BF16(acc[mt][nt], al[mt], bh[np][hf], bh[np][hf + 1]);
                }
            }
        }
        __syncthreads();
    }

    // epilogue: c frag m16n8 — thread holds (r, c0..c1) and (r+8, c0..c1)
#pragma unroll
    for (int mt = 0; mt < 2; mt++) {
        int r0 = wm * 32 + mt * 16 + (lane >> 2);
        float bias0 = __ldg(bo + r0);
        float bias1 = __ldg(bo + r0 + 8);
        float* o0 = out + (size_t)(b * C + r0) * HW + (size_t)y * W;
        float* o1 = o0 + (size_t)8 * HW;
#pragma unroll
        for (int nt = 0; nt < 8; nt++) {
            int xc = wn * 64 + nt * 8 + (lane & 3) * 2;
            *(float2*)&o0[xc] = make_float2(acc[mt][nt][0] + bias0, acc[mt][nt][1] + bias0);
            *(float2*)&o1[xc] = make_float2(acc[mt][nt][2] + bias1, acc[mt][nt][3] + bias1);
        }
    }
}

// ---------------------------------------------------------------------------
extern "C" void kernel_launch(void* const* d_in, const int* in_sizes, int n_in,
                              void* d_out, int out_size) {
    const float* x  = (const float*)d_in[0];
    const float* wq = (const float*)d_in[1];
    const float* bq = (const float*)d_in[2];
    const float* wk = (const float*)d_in[3];
    const float* bk = (const float*)d_in[4];
    const float* wv = (const float*)d_in[5];
    const float* bv = (const float*)d_in[6];
    const float* wo = (const float*)d_in[7];
    const float* bo = (const float*)d_in[8];
    float* out = (float*)d_out;

    cudaFuncSetAttribute(out_conv_mma, cudaFuncAttributeMaxDynamicSharedMemorySize, SMEM_TOTAL);

    prep_w<<<(C * C * 9 + 255) / 256, 256>>>(wo);
    qkv_dwconv<<<dim3(W / 64, H / 32, B * C), 256>>>(x, wq, bq, wk, bk, wv, bv);
    score_gemm<<<dim3(2, B * NH), dim3(16, 16)>>>();
    softmax_rows<<<(B * NH * C) / 8, 256>>>();
    pv_gemm<<<dim3(HW / NH / 128, B * NH), dim3(16, 16)>>>();
    out_conv_mma<<<dim3(H, B), 256, SMEM_TOTAL>>>(bo, out);
}

// round 11
// speedup vs baseline: 2.0876x; 1.3384x over previous
#include <cuda_runtime.h>
#include <cuda_bf16.h>
#include <cstdint>

// ---------------------------------------------------------------------------
// MultiheadChannelAttention — R10: score + PV GEMMs moved to mma.sync bf16
// (3-term split), joining out_conv. dwconv emits split-bf16 Q/K directly;
// V transposed to pixel-major by a small kernel; softmax emits split-bf16 P.
// ---------------------------------------------------------------------------

namespace {
constexpr int B = 8, C = 128, H = 128, W = 128;
constexpr int HW = H * W;      // 16384
constexpr int NH = 8;
constexpr int D = HW / NH;     // 2048
constexpr float SCALE = 1.0f / 128.0f;

// 272B-row tiles (128 + 8 pad bf16) for pv / out_conv
constexpr int LDT_B = 272;
constexpr int TILE_B2 = 128 * LDT_B;        // 34816
constexpr int SA_H = 0;
constexpr int SA_L = SA_H + TILE_B2;
constexpr int SB_H = SA_L + TILE_B2;
constexpr int SB_L = SB_H + TILE_B2;
constexpr int SMEM_TOTAL = SB_L + TILE_B2;  // 139264

// score smem: 144B rows (64 bf16 + 8 pad)
constexpr int LDT_S = 144;
constexpr int SQ_H = 0;
constexpr int SQ_L = SQ_H + 64 * LDT_S;     //  9216
constexpr int SK_H = SQ_L + 64 * LDT_S;     // 18432
constexpr int SK_L = SK_H + 128 * LDT_S;    // 36864
constexpr int SMEM_SCORE = SK_L + 128 * LDT_S;  // 55296
}

typedef unsigned long long u64;

// Scratch (device globals: no allocation allowed)
__device__ __nv_bfloat16 g_qh[(size_t)B * C * HW];
__device__ __nv_bfloat16 g_ql[(size_t)B * C * HW];
__device__ __nv_bfloat16 g_kh[(size_t)B * C * HW];
__device__ __nv_bfloat16 g_kl[(size_t)B * C * HW];
__device__ float g_v[(size_t)B * C * HW];
__device__ __nv_bfloat16 g_vth[(size_t)B * HW * C];  // V^T [b][pix][c] hi
__device__ __nv_bfloat16 g_vtl[(size_t)B * HW * C];
__device__ float g_s[B * NH * C * C];                // scores (fp32)
__device__ __nv_bfloat16 g_ph[B * NH * C * C];       // softmax probs split
__device__ __nv_bfloat16 g_pl[B * NH * C * C];
__device__ __nv_bfloat16 g_ah[(size_t)B * HW * C];   // attn out [b][pix][ci]
__device__ __nv_bfloat16 g_al[(size_t)B * HW * C];
__device__ __nv_bfloat16 g_wh[9 * C * C];            // wo split [tap][co][ci]
__device__ __nv_bfloat16 g_wl[9 * C * C];

// ---------------- helpers ---------------------------------------------------
__device__ __forceinline__ uint32_t smem_u32(const void* p) {
    uint32_t a;
    asm("{ .reg .u64 t; cvta.to.shared.u64 t, %1; cvt.u32.u64 %0, t; }" : "=r"(a) : "l"(p));
    return a;
}

#define LDSM4(r, addr)                                                          \
    asm volatile("ldmatrix.sync.aligned.m8n8.x4.shared.b16 {%0,%1,%2,%3}, [%4];" \
        : "=r"((r)[0]), "=r"((r)[1]), "=r"((r)[2]), "=r"((r)[3]) : "r"(addr))

#define MMA_BF16(d, a, b0, b1)                                                  \
    asm volatile("mma.sync.aligned.m16n8k16.row.col.f32.bf16.bf16.f32 "         \
        "{%0,%1,%2,%3}, {%4,%5,%6,%7}, {%8,%9}, {%0,%1,%2,%3};"                 \
        : "+f"((d)[0]), "+f"((d)[1]), "+f"((d)[2]), "+f"((d)[3])                \
        : "r"((a)[0]), "r"((a)[1]), "r"((a)[2]), "r"((a)[3]), "r"(b0), "r"(b1))

union Pack8 { uint4 u; __nv_bfloat16 h[8]; };
union Pack2 { uint32_t u; __nv_bfloat16 h[2]; };

__device__ __forceinline__ uint32_t pack_bf16x2(float a, float b) {
    Pack2 p;
    p.h[0] = __float2bfloat16(a);
    p.h[1] = __float2bfloat16(b);
    return p.u;
}

// ---------------------------------------------------------------------------
// Split wo [co][ci][tap] -> g_wh/g_wl [tap][co][ci] (bf16 hi/lo)
// ---------------------------------------------------------------------------
__global__ void prep_w(const float* __restrict__ wo) {
    int i = blockIdx.x * 256 + threadIdx.x;
    if (i >= C * C * 9) return;
    int co = i / (C * 9);
    int rem = i % (C * 9);
    int ci = rem / 9;
    int tap = rem % 9;
    float w = wo[i];
    __nv_bfloat16 hi = __float2bfloat16(w);
    __nv_bfloat16 lo = __float2bfloat16(w - __bfloat162float(hi));
    int dst = tap * (C * C) + co * C + ci;
    g_wh[dst] = hi;
    g_wl[dst] = lo;
}

// ---------------------------------------------------------------------------
// Fused q/k/v depthwise 9x9 conv (pad 4). q/k written as split bf16,
// v as fp32 (transposed by v_transpose). grid (W/64, H/32, B*C), 256 thr.
// ---------------------------------------------------------------------------
__global__ void __launch_bounds__(256) qkv_dwconv(
        const float* __restrict__ x,
        const float* __restrict__ wq, const float* __restrict__ bq,
        const float* __restrict__ wk, const float* __restrict__ bk,
        const float* __restrict__ wv, const float* __restrict__ bv) {
    __shared__ float tile[40][72];
    __shared__ float wsm[3][81];

    int bc = blockIdx.z;
    int b = bc >> 7, c = bc & 127;
    int x0 = blockIdx.x * 64, y0 = blockIdx.y * 32;
    int tid = threadIdx.x;
    int lane = tid & 7;
    int r = tid >> 3;

    if (tid < 243) {
        int c3 = tid / 81, t = tid % 81;
        const float* wsrc = (c3 == 0) ? wq : (c3 == 1) ? wk : wv;
        wsm[c3][t] = wsrc[c * 81 + t];
    }
    const float* xp = x + (size_t)(b * C + c) * HW;
    for (int i = tid; i < 40 * 72; i += 256) {
        int tr = i / 72, tc = i % 72;
        int gy = y0 - 4 + tr, gx = x0 - 4 + tc;
        float v = 0.0f;
        if ((unsigned)gy < (unsigned)H && (unsigned)gx < (unsigned)W)
            v = xp[gy * W + gx];
        tile[tr][tc] = v;
    }
    __syncthreads();

    float aq[8], ak[8], av[8];
    float biasq = bq[c], biask = bk[c], biasv = bv[c];
#pragma unroll
    for (int p = 0; p < 8; p++) { aq[p] = biasq; ak[p] = biask; av[p] = biasv; }

#pragma unroll
    for (int ky = 0; ky < 9; ky++) {
        float win[16];
        float4 u0 = *(const float4*)&tile[r + ky][lane * 8];
        float4 u1 = *(const float4*)&tile[r + ky][lane * 8 + 4];
        float4 u2 = *(const float4*)&tile[r + ky][lane * 8 + 8];
        float4 u3 = *(const float4*)&tile[r + ky][lane * 8 + 12];
        win[0] = u0.x; win[1] = u0.y; win[2] = u0.z; win[3] = u0.w;
        win[4] = u1.x; win[5] = u1.y; win[6] = u1.z; win[7] = u1.w;
        win[8] = u2.x; win[9] = u2.y; win[10] = u2.z; win[11] = u2.w;
        win[12] = u3.x; win[13] = u3.y; win[14] = u3.z; win[15] = u3.w;
#pragma unroll
        for (int kx = 0; kx < 9; kx++) {
            float w0 = wsm[0][ky * 9 + kx];
            float w1 = wsm[1][ky * 9 + kx];
            float w2 = wsm[2][ky * 9 + kx];
#pragma unroll
            for (int p = 0; p < 8; p++) {
                float vi = win[p + kx];
                aq[p] += vi * w0;
                ak[p] += vi * w1;
                av[p] += vi * w2;
            }
        }
    }

    size_t o = (size_t)(b * C + c) * HW + (size_t)(y0 + r) * W + x0 + lane * 8;
    Pack8 qh, ql, kh, kl;
#pragma unroll
    for (int p = 0; p < 8; p++) {
        __nv_bfloat16 h1 = __float2bfloat16(aq[p]);
        qh.h[p] = h1;
        ql.h[p] = __float2bfloat16(aq[p] - __bfloat162float(h1));
        __nv_bfloat16 h2 = __float2bfloat16(ak[p]);
        kh.h[p] = h2;
        kl.h[p] = __float2bfloat16(ak[p] - __bfloat162float(h2));
    }
    *(uint4*)&g_qh[o] = qh.u;
    *(uint4*)&g_ql[o] = ql.u;
    *(uint4*)&g_kh[o] = kh.u;
    *(uint4*)&g_kl[o] = kl.u;
    *(float4*)&g_v[o]     = make_float4(av[0], av[1], av[2], av[3]);
    *(float4*)&g_v[o + 4] = make_float4(av[4], av[5], av[6], av[7]);
}

// ---------------------------------------------------------------------------
// V^T: g_v [b][c][hw] fp32 -> g_vth/g_vtl [b][pix][c] split bf16.
// grid (HW/32, C/32, B), block (32, 8). smem 32x33 transpose tile.
// ---------------------------------------------------------------------------
__global__ void v_transpose() {
    __shared__ float sm[32][33];
    int p0 = blockIdx.x * 32, c0 = blockIdx.y * 32, b = blockIdx.z;
    int tx = threadIdx.x, ty = threadIdx.y;
    int tid = ty * 32 + tx;

#pragma unroll
    for (int i = 0; i < 4; i++) {
        int c = c0 + ty + i * 8;
        sm[ty + i * 8][tx] = g_v[(size_t)(b * C + c) * HW + p0 + tx];
    }
    __syncthreads();

    // 512 bf16x2 units: p row 0..31, 16 c-pairs
#pragma unroll
    for (int l = 0; l < 2; l++) {
        int i = tid + 256 * l;
        int p = i >> 4, pr = i & 15;
        float a = sm[pr * 2][p];
        float b2 = sm[pr * 2 + 1][p];
        __nv_bfloat16 ha = __float2bfloat16(a);
        __nv_bfloat16 hb = __float2bfloat16(b2);
        Pack2 hi, lo;
        hi.h[0] = ha; hi.h[1] = hb;
        lo.h[0] = __float2bfloat16(a - __bfloat162float(ha));
        lo.h[1] = __float2bfloat16(b2 - __bfloat162float(hb));
        size_t base = ((size_t)b * HW + p0 + p) * C + c0 + pr * 2;
        *(uint32_t*)&g_vth[base] = hi.u;
        *(uint32_t*)&g_vtl[base] = lo.u;
    }
}

// ---------------------------------------------------------------------------
// score_mma: S = (Q K^T)*SCALE per (b,h) via mma.sync, 3-term bf16 split.
// grid (2, B*NH): tile 64(c) x 128(c'), K = 2048 in chunks of 64.
// 8 warps = 2(M) x 4(N), warp tile 32x32.
// ---------------------------------------------------------------------------
__global__ void __launch_bounds__(256) score_mma() {
    extern __shared__ char smem[];
    uint32_t sb = smem_u32(smem);
    const int tid = threadIdx.x;
    const int wid = tid >> 5, lane = tid & 31;
    const int bh = blockIdx.y;
    const int b = bh >> 3, h = bh & 7;
    const int r0 = blockIdx.x * 64;
    const int wm = wid & 1;       // 2 M warps (32 rows each)
    const int wnn = wid >> 1;     // 4 N warps (32 cols each)

    const uint4* qhp = (const uint4*)g_qh;
    const uint4* qlp = (const uint4*)g_ql;
    const uint4* khp = (const uint4*)g_kh;
    const uint4* klp = (const uint4*)g_kl;

    float acc[2][4][4];
#pragma unroll
    for (int mt = 0; mt < 2; mt++)
#pragma unroll
        for (int nt = 0; nt < 4; nt++)
#pragma unroll
            for (int j = 0; j < 4; j++) acc[mt][nt][j] = 0.0f;

    for (int kt = 0; kt < D; kt += 64) {
        size_t qbase = ((size_t)(b * C + r0) * HW + h * D + kt) >> 3;
        size_t kbase = ((size_t)(b * C) * HW + h * D + kt) >> 3;
#pragma unroll
        for (int l = 0; l < 12; l++) {
            int i = tid + 256 * l;       // 0..3071
            if (i < 1024) {              // Q: hi 512, lo 512
                int half = i >> 9, idx = i & 511;
                int row = idx >> 3, g = idx & 7;
                uint32_t off = (uint32_t)row * LDT_S + g * 16;
                size_t gi = qbase + (size_t)row * (HW / 8) + g;
                if (half == 0) *(uint4*)(smem + SQ_H + off) = qhp[gi];
                else           *(uint4*)(smem + SQ_L + off) = qlp[gi];
            } else {                     // K: hi 1024, lo 1024
                int j = i - 1024;
                int half = j >> 10, idx = j & 1023;
                int row = idx >> 3, g = idx & 7;
                uint32_t off = (uint32_t)row * LDT_S + g * 16;
                size_t gi = kbase + (size_t)row * (HW / 8) + g;
                if (half == 0) *(uint4*)(smem + SK_H + off) = khp[gi];
                else           *(uint4*)(smem + SK_L + off) = klp[gi];
            }
        }
        __syncthreads();

#pragma unroll
        for (int ks = 0; ks < 4; ks++) {
            uint32_t ah[2][4], al[2][4], bh[2][4], bl[2][4];
#pragma unroll
            for (int mt = 0; mt < 2; mt++) {
                uint32_t addr = sb + SQ_H
                    + (uint32_t)(wm * 32 + mt * 16 + (lane & 15)) * LDT_S
                    + (uint32_t)(ks * 16 + (lane >> 4) * 8) * 2;
                LDSM4(ah[mt], addr);
                LDSM4(al[mt], addr + (SQ_L - SQ_H));
            }
#pragma unroll
            for (int np = 0; np < 2; np++) {
                int n = wnn * 32 + np * 16 + (lane & 7) + ((lane >> 4) & 1) * 8;
                int ko = ks * 16 + ((lane >> 3) & 1) * 8;
                uint32_t addr = sb + SK_H + (uint32_t)n * LDT_S + (uint32_t)ko * 2;
                LDSM4(bh[np], addr);
                LDSM4(bl[np], addr + (SK_L - SK_H));
            }
#pragma unroll
            for (int mt = 0; mt < 2; mt++) {
#pragma unroll
                for (int nt = 0; nt < 4; nt++) {
                    int np = nt >> 1, hf = (nt & 1) * 2;
                    MMA_BF16(acc[mt][nt], ah[mt], bh[np][hf], bh[np][hf + 1]);
                    MMA_BF16(acc[mt][nt], ah[mt], bl[np][hf], bl[np][hf + 1]);
                    MMA_BF16(acc[mt][nt], al[mt], bh[np][hf], bh[np][hf + 1]);
                }
            }
        }
        __syncthreads();
    }

#pragma unroll
    for (int mt = 0; mt < 2; mt++) {
        int r = r0 + wm * 32 + mt * 16 + (lane >> 2);
#pragma unroll
        for (int nt = 0; nt < 4; nt++) {
            int cc = wnn * 32 + nt * 8 + (lane & 3) * 2;
            *(float2*)&g_s[((size_t)bh * C + r) * C + cc] =
                make_float2(acc[mt][nt][0] * SCALE, acc[mt][nt][1] * SCALE);
            *(float2*)&g_s[((size_t)bh * C + r + 8) * C + cc] =
                make_float2(acc[mt][nt][2] * SCALE, acc[mt][nt][3] * SCALE);
        }
    }
}

// ---------------------------------------------------------------------------
// Row softmax over g_s; writes split bf16 P. One warp per row.
// ---------------------------------------------------------------------------
__global__ void softmax_p() {
    int gw = (blockIdx.x * blockDim.x + threadIdx.x) >> 5;
    int lane = threadIdx.x & 31;
    if (gw >= B * NH * C) return;
    float4 v = *(const float4*)&g_s[(size_t)gw * C + lane * 4];
    float m = fmaxf(fmaxf(v.x, v.y), fmaxf(v.z, v.w));
#pragma unroll
    for (int o = 16; o > 0; o >>= 1)
        m = fmaxf(m, __shfl_xor_sync(0xffffffffu, m, o));
    v.x = __expf(v.x - m);
    v.y = __expf(v.y - m);
    v.z = __expf(v.z - m);
    v.w = __expf(v.w - m);
    float s = v.x + v.y + v.z + v.w;
#pragma unroll
    for (int o = 16; o > 0; o >>= 1)
        s += __shfl_xor_sync(0xffffffffu, s, o);
    float inv = 1.0f / s;
    float p[4] = {v.x * inv, v.y * inv, v.z * inv, v.w * inv};

    Pack2 h0, h1, l0, l1;
#pragma unroll
    for (int j = 0; j < 4; j++) {
        __nv_bfloat16 hi = __float2bfloat16(p[j]);
        __nv_bfloat16 lo = __float2bfloat16(p[j] - __bfloat162float(hi));
        if (j < 2) { h0.h[j] = hi; l0.h[j] = lo; }
        else       { h1.h[j - 2] = hi; l1.h[j - 2] = lo; }
    }
    size_t base = (size_t)gw * C + lane * 4;
    *(uint32_t*)&g_ph[base]     = h0.u;
    *(uint32_t*)&g_ph[base + 2] = h1.u;
    *(uint32_t*)&g_pl[base]     = l0.u;
    *(uint32_t*)&g_pl[base + 2] = l1.u;
}

// ---------------------------------------------------------------------------
// pv_mma: out[pix][c] = sum_e V^T[pix][e] * P[c][e], per (b,h) tile of
// 128 pix x 128 c, K = 128. grid (16, B*NH). 8 warps = 4(M pix) x 2(N c).
// Writes split bf16 g_ah/g_al [b][pix][ci] (out_conv's input layout).
// ---------------------------------------------------------------------------
__global__ void __launch_bounds__(256) pv_mma() {
    extern __shared__ char smem[];
    uint32_t sb = smem_u32(smem);
    const int tid = threadIdx.x;
    const int wid = tid >> 5, lane = tid & 31;
    const int bh = blockIdx.y;
    const int b = bh >> 3, h = bh & 7;
    const int dt = blockIdx.x * 128;
    const int wm = wid & 3;      // M warp: 32 pix
    const int wn = wid >> 2;     // N warp: 64 c

    const uint4* vhp = (const uint4*)g_vth;
    const uint4* vlp = (const uint4*)g_vtl;
    const uint4* php = (const uint4*)g_ph;
    const uint4* plp = (const uint4*)g_pl;

    // stage: A = V^T rows (pix), B = P rows (c); both k = e contiguous
    size_t abase = ((size_t)b * HW + h * D + dt) * C >> 3;
    size_t bbase = (size_t)bh * C * C >> 3;
#pragma unroll
    for (int l = 0; l < 32; l++) {
        int i = tid + 256 * l;           // 0..8191
        int region = i >> 11, idx = i & 2047;
        int row = idx >> 4, cg = idx & 15;
        uint32_t off = (uint32_t)row * LDT_B + cg * 16;
        if (region == 0)
            *(uint4*)(smem + SA_H + off) = vhp[abase + (size_t)row * 16 + cg];
        else if (region == 1)
            *(uint4*)(smem + SA_L + off) = vlp[abase + (size_t)row * 16 + cg];
        else if (region == 2)
            *(uint4*)(smem + SB_H + off) = php[bbase + (size_t)row * 16 + cg];
        else
            *(uint4*)(smem + SB_L + off) = plp[bbase + (size_t)row * 16 + cg];
    }
    __syncthreads();

    float acc[2][8][4];
#pragma unroll
    for (int mt = 0; mt < 2; mt++)
#pragma unroll
        for (int nt = 0; nt < 8; nt++)
#pragma unroll
            for (int j = 0; j < 4; j++) acc[mt][nt][j] = 0.0f;

#pragma unroll
    for (int ks = 0; ks < 8; ks++) {
        uint32_t ah[2][4], al[2][4], bh[4][4], bl[4][4];
#pragma unroll
        for (int mt = 0; mt < 2; mt++) {
            uint32_t addr = sb + SA_H
                + (uint32_t)(wm * 32 + mt * 16 + (lane & 15)) * LDT_B
                + (uint32_t)(ks * 16 + (lane >> 4) * 8) * 2;
            LDSM4(ah[mt], addr);
            LDSM4(al[mt], addr + (SA_L - SA_H));
        }
#pragma unroll
        for (int np = 0; np < 4; np++) {
            int n = wn * 64 + np * 16 + (lane & 7) + ((lane >> 4) & 1) * 8;
            int ko = ks * 16 + ((lane >> 3) & 1) * 8;
            uint32_t addr = sb + SB_H + (uint32_t)n * LDT_B + (uint32_t)ko * 2;
            LDSM4(bh[np], addr);
            LDSM4(bl[np], addr + (SB_L - SB_H));
        }
#pragma unroll
        for (int mt = 0; mt < 2; mt++) {
#pragma unroll
            for (int nt = 0; nt < 8; nt++) {
                int np = nt >> 1, hf = (nt & 1) * 2;
                MMA_BF16(acc[mt][nt], ah[mt], bh[np][hf], bh[np][hf + 1]);
                MMA_BF16(acc[mt][nt], ah[mt], bl[np][hf], bl[np][hf + 1]);
                MMA_BF16(acc[mt][nt], al[mt], bh[np][hf], bh[np][hf + 1]);
            }
        }
    }

    // epilogue: (m=pix, n=c) — c pairs contiguous -> bf16x2 stores
#pragma unroll
    for (int mt = 0; mt < 2; mt++) {
        size_t pix0 = (size_t)b * HW + h * D + dt + wm * 32 + mt * 16 + (lane >> 2);
#pragma unroll
        for (int nt = 0; nt < 8; nt++) {
            int c0 = wn * 64 + nt * 8 + (lane & 3) * 2;
            float a0 = acc[mt][nt][0], a1 = acc[mt][nt][1];
            float a2 = acc[mt][nt][2], a3 = acc[mt][nt][3];
            __nv_bfloat16 h0 = __float2bfloat16(a0);
            __nv_bfloat16 h1 = __float2bfloat16(a1);
            __nv_bfloat16 h2 = __float2bfloat16(a2);
            __nv_bfloat16 h3 = __float2bfloat16(a3);
            Pack2 ph0, pl0, ph1, pl1;
            ph0.h[0] = h0; ph0.h[1] = h1;
            pl0.h[0] = __float2bfloat16(a0 - __bfloat162float(h0));
            pl0.h[1] = __float2bfloat16(a1 - __bfloat162float(h1));
            ph1.h[0] = h2; ph1.h[1] = h3;
            pl1.h[0] = __float2bfloat16(a2 - __bfloat162float(h2));
            pl1.h[1] = __float2bfloat16(a3 - __bfloat162float(h3));
            *(uint32_t*)&g_ah[pix0 * C + c0]       = ph0.u;
            *(uint32_t*)&g_al[pix0 * C + c0]       = pl0.u;
            *(uint32_t*)&g_ah[(pix0 + 8) * C + c0] = ph1.u;
            *(uint32_t*)&g_al[(pix0 + 8) * C + c0] = pl1.u;
        }
    }
}

// ---------------------------------------------------------------------------
// out_conv via mma.sync bf16 (unchanged from R9). grid (H, B), 256 threads.
// ---------------------------------------------------------------------------
__global__ void __launch_bounds__(256) out_conv_mma(const float* __restrict__ bo,
                                                    float* __restrict__ out) {
    extern __shared__ char smem[];
    uint32_t sb = smem_u32(smem);
    const int tid = threadIdx.x;
    const int wid = tid >> 5, lane = tid & 31;
    const int y = blockIdx.x, b = blockIdx.y;
    const int wm = wid & 3;
    const int wn = wid >> 2;

    float acc[2][8][4];
#pragma unroll
    for (int mt = 0; mt < 2; mt++)
#pragma unroll
        for (int nt = 0; nt < 8; nt++)
#pragma unroll
            for (int j = 0; j < 4; j++) acc[mt][nt][j] = 0.0f;

    const uint4* whp = (const uint4*)g_wh;
    const uint4* wlp = (const uint4*)g_wl;
    const uint4* ahp = (const uint4*)g_ah;
    const uint4* alp = (const uint4*)g_al;
    const uint4 z4 = make_uint4(0, 0, 0, 0);

    for (int tap = 0; tap < 9; tap++) {
        int dy = tap / 3, dx = tap % 3;
        int yy = y + dy - 1;
        bool yok = (unsigned)yy < (unsigned)H;

#pragma unroll
        for (int l = 0; l < 8; l++) {
            int i = tid + 256 * l;
            int row = i >> 4, cg = i & 15;
            uint32_t off = (uint32_t)row * LDT_B + cg * 16;
            size_t widx = (size_t)tap * 2048 + row * 16 + cg;
            *(uint4*)(smem + SA_H + off) = whp[widx];
            *(uint4*)(smem + SA_L + off) = wlp[widx];
            int xx = row + dx - 1;
            uint4 vh = z4, vl = z4;
            if (yok && (unsigned)xx < (unsigned)W) {
                size_t aidx = ((size_t)b * HW + yy * W + xx) * 16 + cg;
                vh = ahp[aidx];
                vl = alp[aidx];
            }
            *(uint4*)(smem + SB_H + off) = vh;
            *(uint4*)(smem + SB_L + off) = vl;
        }
        __syncthreads();

#pragma unroll
        for (int ks = 0; ks < 8; ks++) {
            uint32_t ah[2][4], al[2][4], bh[4][4], bl[4][4];
#pragma unroll
            for (int mt = 0; mt < 2; mt++) {
                uint32_t addr = sb + SA_H
                    + (uint32_t)(wm * 32 + mt * 16 + (lane & 15)) * LDT_B
                    + (uint32_t)(ks * 16 + (lane >> 4) * 8) * 2;
                LDSM4(ah[mt], addr);
                LDSM4(al[mt], addr + (SA_L - SA_H));
            }
#pragma unroll
            for (int np = 0; np < 4; np++) {
                int n = wn * 64 + np * 16 + (lane & 7) + ((lane >> 4) & 1) * 8;
                int ko = ks * 16 + ((lane >> 3) & 1) * 8;
                uint32_t addr = sb + SB_H + (uint32_t)n * LDT_B + (uint32_t)ko * 2;
                LDSM4(bh[np], addr);
                LDSM4(bl[np], addr + (SB_L - SB_H));
            }
#pragma unroll
            for (int mt = 0; mt < 2; mt++) {
#pragma unroll
                for (int nt = 0; nt < 8; nt++) {
                    int np = nt >> 1, hf = (nt & 1) * 2;
                    MMA_BF16(acc[mt][nt], ah[mt], bh[np][hf], bh[np][hf + 1]);
                    MMA_BF16(acc[mt][nt], ah[mt], bl[np][hf], bl[np][hf + 1]);
                    MMA_BF16(acc[mt][nt], al[mt], bh[np][hf], bh[np][hf + 1]);
                }
            }
        }
        __syncthreads();
    }

#pragma unroll
    for (int mt = 0; mt < 2; mt++) {
        int r0 = wm * 32 + mt * 16 + (lane >> 2);
        float bias0 = __ldg(bo + r0);
        float bias1 = __ldg(bo + r0 + 8);
        float* o0 = out + (size_t)(b * C + r0) * HW + (size_t)y * W;
        float* o1 = o0 + (size_t)8 * HW;
#pragma unroll
        for (int nt = 0; nt < 8; nt++) {
            int xc = wn * 64 + nt * 8 + (lane & 3) * 2;
            *(float2*)&o0[xc] = make_float2(acc[mt][nt][0] + bias0, acc[mt][nt][1] + bias0);
            *(float2*)&o1[xc] = make_float2(acc[mt][nt][2] + bias1, acc[mt][nt][3] + bias1);
        }
    }
}

// ---------------------------------------------------------------------------
extern "C" void kernel_launch(void* const* d_in, const int* in_sizes, int n_in,
                              void* d_out, int out_size) {
    const float* x  = (const float*)d_in[0];
    const float* wq = (const float*)d_in[1];
    const float* bq = (const float*)d_in[2];
    const float* wk = (const float*)d_in[3];
    const float* bk = (const float*)d_in[4];
    const float* wv = (const float*)d_in[5];
    const float* bv = (const float*)d_in[6];
    const float* wo = (const float*)d_in[7];
    const float* bo = (const float*)d_in[8];
    float* out = (float*)d_out;

    cudaFuncSetAttribute(score_mma,    cudaFuncAttributeMaxDynamicSharedMemorySize, SMEM_SCORE);
    cudaFuncSetAttribute(pv_mma,       cudaFuncAttributeMaxDynamicSharedMemorySize, SMEM_TOTAL);
    cudaFuncSetAttribute(out_conv_mma, cudaFuncAttributeMaxDynamicSharedMemorySize, SMEM_TOTAL);

    prep_w<<<(C * C * 9 + 255) / 256, 256>>>(wo);
    qkv_dwconv<<<dim3(W / 64, H / 32, B * C), 256>>>(x, wq, bq, wk, bk, wv, bv);
    v_transpose<<<dim3(HW / 32, C / 32, B), dim3(32, 8)>>>();
    score_mma<<<dim3(2, B * NH), 256, SMEM_SCORE>>>();
    softmax_p<<<(B * NH * C) / 8, 256>>>();
    pv_mma<<<dim3(HW / NH / 128, B * NH), 256, SMEM_TOTAL>>>();
    out_conv_mma<<<dim3(H, B), 256, SMEM_TOTAL>>>(bo, out);
}

// round 13
// speedup vs baseline: 2.2040x; 1.0557x over previous
#include <cuda_runtime.h>
#include <cuda_bf16.h>
#include <cstdint>

// ---------------------------------------------------------------------------
// MultiheadChannelAttention — R11: score_mma retiled to 64x64 (2 CTAs/SM),
// out_conv converted to cp.async double-buffered pipeline (18 stages of
// 64-ci chunks). Everything else from R10 (739 µs).
// ---------------------------------------------------------------------------

namespace {
constexpr int B = 8, C = 128, H = 128, W = 128;
constexpr int HW = H * W;      // 16384
constexpr int NH = 8;
constexpr int D = HW / NH;     // 2048
constexpr float SCALE = 1.0f / 128.0f;

// pv tiles: 272B rows (128 + 8 pad bf16)
constexpr int LDT_B = 272;
constexpr int TILE_B2 = 128 * LDT_B;        // 34816
constexpr int SA_H = 0;
constexpr int SA_L = SA_H + TILE_B2;
constexpr int SB_H = SA_L + TILE_B2;
constexpr int SB_L = SB_H + TILE_B2;
constexpr int SMEM_PV = SB_L + TILE_B2;     // 139264

// score tiles: 144B rows (64 bf16 + 8 pad), 64 rows each
constexpr int LDT_S = 144;
constexpr int SCT = 64 * LDT_S;             // 9216 per tile
constexpr int SQ_H = 0, SQ_L = SCT, SK_H = 2 * SCT, SK_L = 3 * SCT;
constexpr int SMEM_SCORE = 4 * SCT;         // 36864

// out_conv pipeline: per-buffer 4 tiles of 128 rows x 144B = 18432 each
constexpr int OC_TILE = 128 * LDT_S;        // 18432
constexpr int OC_BUF = 4 * OC_TILE;         // 73728
constexpr int SMEM_OC = 2 * OC_BUF;         // 147456
}

typedef unsigned long long u64;

// Scratch (device globals: no allocation allowed)
__device__ __nv_bfloat16 g_qh[(size_t)B * C * HW];
__device__ __nv_bfloat16 g_ql[(size_t)B * C * HW];
__device__ __nv_bfloat16 g_kh[(size_t)B * C * HW];
__device__ __nv_bfloat16 g_kl[(size_t)B * C * HW];
__device__ float g_v[(size_t)B * C * HW];
__device__ __nv_bfloat16 g_vth[(size_t)B * HW * C];  // V^T [b][pix][c] hi
__device__ __nv_bfloat16 g_vtl[(size_t)B * HW * C];
__device__ float g_s[B * NH * C * C];                // scores (fp32)
__device__ __nv_bfloat16 g_ph[B * NH * C * C];       // softmax probs split
__device__ __nv_bfloat16 g_pl[B * NH * C * C];
__device__ __nv_bfloat16 g_ah[(size_t)B * HW * C];   // attn out [b][pix][ci]
__device__ __nv_bfloat16 g_al[(size_t)B * HW * C];
__device__ __nv_bfloat16 g_wh[9 * C * C];            // wo split [tap][co][ci]
__device__ __nv_bfloat16 g_wl[9 * C * C];

// ---------------- helpers ---------------------------------------------------
__device__ __forceinline__ uint32_t smem_u32(const void* p) {
    uint32_t a;
    asm("{ .reg .u64 t; cvta.to.shared.u64 t, %1; cvt.u32.u64 %0, t; }" : "=r"(a) : "l"(p));
    return a;
}

__device__ __forceinline__ void cp16(uint32_t dst, const void* src, bool ok) {
    int sz = ok ? 16 : 0;
    asm volatile("cp.async.cg.shared.global [%0], [%1], 16, %2;"
                 :: "r"(dst), "l"(src), "r"(sz) : "memory");
}
#define CP_COMMIT() asm volatile("cp.async.commit_group;" ::: "memory")

#define LDSM4(r, addr)                                                          \
    asm volatile("ldmatrix.sync.aligned.m8n8.x4.shared.b16 {%0,%1,%2,%3}, [%4];" \
        : "=r"((r)[0]), "=r"((r)[1]), "=r"((r)[2]), "=r"((r)[3]) : "r"(addr))

#define MMA_BF16(d, a, b0, b1)                                                  \
    asm volatile("mma.sync.aligned.m16n8k16.row.col.f32.bf16.bf16.f32 "         \
        "{%0,%1,%2,%3}, {%4,%5,%6,%7}, {%8,%9}, {%0,%1,%2,%3};"                 \
        : "+f"((d)[0]), "+f"((d)[1]), "+f"((d)[2]), "+f"((d)[3])                \
        : "r"((a)[0]), "r"((a)[1]), "r"((a)[2]), "r"((a)[3]), "r"(b0), "r"(b1))

union Pack8 { uint4 u; __nv_bfloat16 h[8]; };
union Pack2 { uint32_t u; __nv_bfloat16 h[2]; };

// ---------------------------------------------------------------------------
// Split wo [co][ci][tap] -> g_wh/g_wl [tap][co][ci] (bf16 hi/lo)
// ---------------------------------------------------------------------------
__global__ void prep_w(const float* __restrict__ wo) {
    int i = blockIdx.x * 256 + threadIdx.x;
    if (i >= C * C * 9) return;
    int co = i / (C * 9);
    int rem = i % (C * 9);
    int ci = rem / 9;
    int tap = rem % 9;
    float w = wo[i];
    __nv_bfloat16 hi = __float2bfloat16(w);
    __nv_bfloat16 lo = __float2bfloat16(w - __bfloat162float(hi));
    int dst = tap * (C * C) + co * C + ci;
    g_wh[dst] = hi;
    g_wl[dst] = lo;
}

// ---------------------------------------------------------------------------
// Fused q/k/v depthwise 9x9 conv (pad 4). q/k split bf16, v fp32.
// ---------------------------------------------------------------------------
__global__ void __launch_bounds__(256) qkv_dwconv(
        const float* __restrict__ x,
        const float* __restrict__ wq, const float* __restrict__ bq,
        const float* __restrict__ wk, const float* __restrict__ bk,
        const float* __restrict__ wv, const float* __restrict__ bv) {
    __shared__ float tile[40][72];
    __shared__ float wsm[3][81];

    int bc = blockIdx.z;
    int b = bc >> 7, c = bc & 127;
    int x0 = blockIdx.x * 64, y0 = blockIdx.y * 32;
    int tid = threadIdx.x;
    int lane = tid & 7;
    int r = tid >> 3;

    if (tid < 243) {
        int c3 = tid / 81, t = tid % 81;
        const float* wsrc = (c3 == 0) ? wq : (c3 == 1) ? wk : wv;
        wsm[c3][t] = wsrc[c * 81 + t];
    }
    const float* xp = x + (size_t)(b * C + c) * HW;
    for (int i = tid; i < 40 * 72; i += 256) {
        int tr = i / 72, tc = i % 72;
        int gy = y0 - 4 + tr, gx = x0 - 4 + tc;
        float v = 0.0f;
        if ((unsigned)gy < (unsigned)H && (unsigned)gx < (unsigned)W)
            v = xp[gy * W + gx];
        tile[tr][tc] = v;
    }
    __syncthreads();

    float aq[8], ak[8], av[8];
    float biasq = bq[c], biask = bk[c], biasv = bv[c];
#pragma unroll
    for (int p = 0; p < 8; p++) { aq[p] = biasq; ak[p] = biask; av[p] = biasv; }

#pragma unroll
    for (int ky = 0; ky < 9; ky++) {
        float win[16];
        float4 u0 = *(const float4*)&tile[r + ky][lane * 8];
        float4 u1 = *(const float4*)&tile[r + ky][lane * 8 + 4];
        float4 u2 = *(const float4*)&tile[r + ky][lane * 8 + 8];
        float4 u3 = *(const float4*)&tile[r + ky][lane * 8 + 12];
        win[0] = u0.x; win[1] = u0.y; win[2] = u0.z; win[3] = u0.w;
        win[4] = u1.x; win[5] = u1.y; win[6] = u1.z; win[7] = u1.w;
        win[8] = u2.x; win[9] = u2.y; win[10] = u2.z; win[11] = u2.w;
        win[12] = u3.x; win[13] = u3.y; win[14] = u3.z; win[15] = u3.w;
#pragma unroll
        for (int kx = 0; kx < 9; kx++) {
            float w0 = wsm[0][ky * 9 + kx];
            float w1 = wsm[1][ky * 9 + kx];
            float w2 = wsm[2][ky * 9 + kx];
#pragma unroll
            for (int p = 0; p < 8; p++) {
                float vi = win[p + kx];
                aq[p] += vi * w0;
                ak[p] += vi * w1;
                av[p] += vi * w2;
            }
        }
    }

    size_t o = (size_t)(b * C + c) * HW + (size_t)(y0 + r) * W + x0 + lane * 8;
    Pack8 qh, ql, kh, kl;
#pragma unroll
    for (int p = 0; p < 8; p++) {
        __nv_bfloat16 h1 = __float2bfloat16(aq[p]);
        qh.h[p] = h1;
        ql.h[p] = __float2bfloat16(aq[p] - __bfloat162float(h1));
        __nv_bfloat16 h2 = __float2bfloat16(ak[p]);
        kh.h[p] = h2;
        kl.h[p] = __float2bfloat16(ak[p] - __bfloat162float(h2));
    }
    *(uint4*)&g_qh[o] = qh.u;
    *(uint4*)&g_ql[o] = ql.u;
    *(uint4*)&g_kh[o] = kh.u;
    *(uint4*)&g_kl[o] = kl.u;
    *(float4*)&g_v[o]     = make_float4(av[0], av[1], av[2], av[3]);
    *(float4*)&g_v[o + 4] = make_float4(av[4], av[5], av[6], av[7]);
}

// ---------------------------------------------------------------------------
// V^T: g_v [b][c][hw] fp32 -> g_vth/g_vtl [b][pix][c] split bf16.
// ---------------------------------------------------------------------------
__global__ void v_transpose() {
    __shared__ float sm[32][33];
    int p0 = blockIdx.x * 32, c0 = blockIdx.y * 32, b = blockIdx.z;
    int tx = threadIdx.x, ty = threadIdx.y;
    int tid = ty * 32 + tx;

#pragma unroll
    for (int i = 0; i < 4; i++) {
        int c = c0 + ty + i * 8;
        sm[ty + i * 8][tx] = g_v[(size_t)(b * C + c) * HW + p0 + tx];
    }
    __syncthreads();

#pragma unroll
    for (int l = 0; l < 2; l++) {
        int i = tid + 256 * l;
        int p = i >> 4, pr = i & 15;
        float a = sm[pr * 2][p];
        float b2 = sm[pr * 2 + 1][p];
        __nv_bfloat16 ha = __float2bfloat16(a);
        __nv_bfloat16 hb = __float2bfloat16(b2);
        Pack2 hi, lo;
        hi.h[0] = ha; hi.h[1] = hb;
        lo.h[0] = __float2bfloat16(a - __bfloat162float(ha));
        lo.h[1] = __float2bfloat16(b2 - __bfloat162float(hb));
        size_t base = ((size_t)b * HW + p0 + p) * C + c0 + pr * 2;
        *(uint32_t*)&g_vth[base] = hi.u;
        *(uint32_t*)&g_vtl[base] = lo.u;
    }
}

// ---------------------------------------------------------------------------
// score_mma: S = (Q K^T)*SCALE per (b,h); 64x64 tiles, grid (4, B*NH)=256
// CTAs -> 2 CTAs/SM for latency hiding. K=2048 in chunks of 64.
// 8 warps = 2(M:32) x 4(N:16).
// ---------------------------------------------------------------------------
__global__ void __launch_bounds__(256) score_mma() {
    extern __shared__ char smem[];
    uint32_t sb = smem_u32(smem);
    const int tid = threadIdx.x;
    const int wid = tid >> 5, lane = tid & 31;
    const int bh = blockIdx.y;
    const int b = bh >> 3, h = bh & 7;
    const int quad = blockIdx.x;
    const int r0 = (quad >> 1) * 64, c0 = (quad & 1) * 64;
    const int wm = wid & 1;       // 2 M warps (32 rows each)
    const int wn = wid >> 1;      // 4 N warps (16 cols each)

    const uint4* qhp = (const uint4*)g_qh;
    const uint4* qlp = (const uint4*)g_ql;
    const uint4* khp = (const uint4*)g_kh;
    const uint4* klp = (const uint4*)g_kl;

    float acc[2][2][4];
#pragma unroll
    for (int mt = 0; mt < 2; mt++)
#pragma unroll
        for (int nt = 0; nt < 2; nt++)
#pragma unroll
            for (int j = 0; j < 4; j++) acc[mt][nt][j] = 0.0f;

    for (int kt = 0; kt < D; kt += 64) {
        size_t qbase = ((size_t)(b * C + r0) * HW + h * D + kt) >> 3;
        size_t kbase = ((size_t)(b * C + c0) * HW + h * D + kt) >> 3;
#pragma unroll
        for (int l = 0; l < 8; l++) {
            int i = tid + 256 * l;       // 0..2047
            int region = i >> 9, idx = i & 511;
            int row = idx >> 3, g = idx & 7;
            uint32_t off = (uint32_t)row * LDT_S + g * 16;
            if (region == 0)
                *(uint4*)(smem + SQ_H + off) = qhp[qbase + (size_t)row * (HW / 8) + g];
            else if (region == 1)
                *(uint4*)(smem + SQ_L + off) = qlp[qbase + (size_t)row * (HW / 8) + g];
            else if (region == 2)
                *(uint4*)(smem + SK_H + off) = khp[kbase + (size_t)row * (HW / 8) + g];
            else
                *(uint4*)(smem + SK_L + off) = klp[kbase + (size_t)row * (HW / 8) + g];
        }
        __syncthreads();

#pragma unroll
        for (int ks = 0; ks < 4; ks++) {
            uint32_t ah[2][4], al[2][4], bh[4], bl[4];
#pragma unroll
            for (int mt = 0; mt < 2; mt++) {
                uint32_t addr = sb + SQ_H
                    + (uint32_t)(wm * 32 + mt * 16 + (lane & 15)) * LDT_S
                    + (uint32_t)(ks * 16 + (lane >> 4) * 8) * 2;
                LDSM4(ah[mt], addr);
                LDSM4(al[mt], addr + (SQ_L - SQ_H));
            }
            {
                int n = wn * 16 + (lane & 7) + ((lane >> 4) & 1) * 8;
                int ko = ks * 16 + ((lane >> 3) & 1) * 8;
                uint32_t addr = sb + SK_H + (uint32_t)n * LDT_S + (uint32_t)ko * 2;
                LDSM4(bh, addr);
                LDSM4(bl, addr + (SK_L - SK_H));
            }
#pragma unroll
            for (int mt = 0; mt < 2; mt++) {
#pragma unroll
                for (int nt = 0; nt < 2; nt++) {
                    int hf = nt * 2;
                    MMA_BF16(acc[mt][nt], ah[mt], bh[hf], bh[hf + 1]);
                    MMA_BF16(acc[mt][nt], ah[mt], bl[hf], bl[hf + 1]);
                    MMA_BF16(acc[mt][nt], al[mt], bh[hf], bh[hf + 1]);
                }
            }
        }
        __syncthreads();
    }

#pragma unroll
    for (int mt = 0; mt < 2; mt++) {
        int r = r0 + wm * 32 + mt * 16 + (lane >> 2);
#pragma unroll
        for (int nt = 0; nt < 2; nt++) {
            int cc = c0 + wn * 16 + nt * 8 + (lane & 3) * 2;
            *(float2*)&g_s[((size_t)bh * C + r) * C + cc] =
                make_float2(acc[mt][nt][0] * SCALE, acc[mt][nt][1] * SCALE);
            *(float2*)&g_s[((size_t)bh * C + r + 8) * C + cc] =
                make_float2(acc[mt][nt][2] * SCALE, acc[mt][nt][3] * SCALE);
        }
    }
}

// ---------------------------------------------------------------------------
// Row softmax over g_s; writes split bf16 P. One warp per row.
// ---------------------------------------------------------------------------
__global__ void softmax_p() {
    int gw = (blockIdx.x * blockDim.x + threadIdx.x) >> 5;
    int lane = threadIdx.x & 31;
    if (gw >= B * NH * C) return;
    float4 v = *(const float4*)&g_s[(size_t)gw * C + lane * 4];
    float m = fmaxf(fmaxf(v.x, v.y), fmaxf(v.z, v.w));
#pragma unroll
    for (int o = 16; o > 0; o >>= 1)
        m = fmaxf(m, __shfl_xor_sync(0xffffffffu, m, o));
    v.x = __expf(v.x - m);
    v.y = __expf(v.y - m);
    v.z = __expf(v.z - m);
    v.w = __expf(v.w - m);
    float s = v.x + v.y + v.z + v.w;
#pragma unroll
    for (int o = 16; o > 0; o >>= 1)
        s += __shfl_xor_sync(0xffffffffu, s, o);
    float inv = 1.0f / s;
    float p[4] = {v.x * inv, v.y * inv, v.z * inv, v.w * inv};

    Pack2 h0, h1, l0, l1;
#pragma unroll
    for (int j = 0; j < 4; j++) {
        __nv_bfloat16 hi = __float2bfloat16(p[j]);
        __nv_bfloat16 lo = __float2bfloat16(p[j] - __bfloat162float(hi));
        if (j < 2) { h0.h[j] = hi; l0.h[j] = lo; }
        else       { h1.h[j - 2] = hi; l1.h[j - 2] = lo; }
    }
    size_t base = (size_t)gw * C + lane * 4;
    *(uint32_t*)&g_ph[base]     = h0.u;
    *(uint32_t*)&g_ph[base + 2] = h1.u;
    *(uint32_t*)&g_pl[base]     = l0.u;
    *(uint32_t*)&g_pl[base + 2] = l1.u;
}

// ---------------------------------------------------------------------------
// pv_mma: out[pix][c] = sum_e V^T[pix][e] * P[c][e] (unchanged from R10).
// ---------------------------------------------------------------------------
__global__ void __launch_bounds__(256) pv_mma() {
    extern __shared__ char smem[];
    uint32_t sb = smem_u32(smem);
    const int tid = threadIdx.x;
    const int wid = tid >> 5, lane = tid & 31;
    const int bh = blockIdx.y;
    const int b = bh >> 3, h = bh & 7;
    const int dt = blockIdx.x * 128;
    const int wm = wid & 3;
    const int wn = wid >> 2;

    const uint4* vhp = (const uint4*)g_vth;
    const uint4* vlp = (const uint4*)g_vtl;
    const uint4* php = (const uint4*)g_ph;
    const uint4* plp = (const uint4*)g_pl;

    size_t abase = ((size_t)b * HW + h * D + dt) * C >> 3;
    size_t bbase = (size_t)bh * C * C >> 3;
#pragma unroll
    for (int l = 0; l < 32; l++) {
        int i = tid + 256 * l;
        int region = i >> 11, idx = i & 2047;
        int row = idx >> 4, cg = idx & 15;
        uint32_t off = (uint32_t)row * LDT_B + cg * 16;
        if (region == 0)
            *(uint4*)(smem + SA_H + off) = vhp[abase + (size_t)row * 16 + cg];
        else if (region == 1)
            *(uint4*)(smem + SA_L + off) = vlp[abase + (size_t)row * 16 + cg];
        else if (region == 2)
            *(uint4*)(smem + SB_H + off) = php[bbase + (size_t)row * 16 + cg];
        else
            *(uint4*)(smem + SB_L + off) = plp[bbase + (size_t)row * 16 + cg];
    }
    __syncthreads();

    float acc[2][8][4];
#pragma unroll
    for (int mt = 0; mt < 2; mt++)
#pragma unroll
        for (int nt = 0; nt < 8; nt++)
#pragma unroll
            for (int j = 0; j < 4; j++) acc[mt][nt][j] = 0.0f;

#pragma unroll
    for (int ks = 0; ks < 8; ks++) {
        uint32_t ah[2][4], al[2][4], bh[4][4], bl[4][4];
#pragma unroll
        for (int mt = 0; mt < 2; mt++) {
            uint32_t addr = sb + SA_H
                + (uint32_t)(wm * 32 + mt * 16 + (lane & 15)) * LDT_B
                + (uint32_t)(ks * 16 + (lane >> 4) * 8) * 2;
            LDSM4(ah[mt], addr);
            LDSM4(al[mt], addr + (SA_L - SA_H));
        }
#pragma unroll
        for (int np = 0; np < 4; np++) {
            int n = wn * 64 + np * 16 + (lane & 7) + ((lane >> 4) & 1) * 8;
            int ko = ks * 16 + ((lane >> 3) & 1) * 8;
            uint32_t addr = sb + SB_H + (uint32_t)n * LDT_B + (uint32_t)ko * 2;
            LDSM4(bh[np], addr);
            LDSM4(bl[np], addr + (SB_L - SB_H));
        }
#pragma unroll
        for (int mt = 0; mt < 2; mt++) {
#pragma unroll
            for (int nt = 0; nt < 8; nt++) {
                int np = nt >> 1, hf = (nt & 1) * 2;
                MMA_BF16(acc[mt][nt], ah[mt], bh[np][hf], bh[np][hf + 1]);
                MMA_BF16(acc[mt][nt], ah[mt], bl[np][hf], bl[np][hf + 1]);
                MMA_BF16(acc[mt][nt], al[mt], bh[np][hf], bh[np][hf + 1]);
            }
        }
    }

#pragma unroll
    for (int mt = 0; mt < 2; mt++) {
        size_t pix0 = (size_t)b * HW + h * D + dt + wm * 32 + mt * 16 + (lane >> 2);
#pragma unroll
        for (int nt = 0; nt < 8; nt++) {
            int c0 = wn * 64 + nt * 8 + (lane & 3) * 2;
            float a0 = acc[mt][nt][0], a1 = acc[mt][nt][1];
            float a2 = acc[mt][nt][2], a3 = acc[mt][nt][3];
            __nv_bfloat16 h0 = __float2bfloat16(a0);
            __nv_bfloat16 h1 = __float2bfloat16(a1);
            __nv_bfloat16 h2 = __float2bfloat16(a2);
            __nv_bfloat16 h3 = __float2bfloat16(a3);
            Pack2 ph0, pl0, ph1, pl1;
            ph0.h[0] = h0; ph0.h[1] = h1;
            pl0.h[0] = __float2bfloat16(a0 - __bfloat162float(h0));
            pl0.h[1] = __float2bfloat16(a1 - __bfloat162float(h1));
            ph1.h[0] = h2; ph1.h[1] = h3;
            pl1.h[0] = __float2bfloat16(a2 - __bfloat162float(h2));
            pl1.h[1] = __float2bfloat16(a3 - __bfloat162float(h3));
            *(uint32_t*)&g_ah[pix0 * C + c0]       = ph0.u;
            *(uint32_t*)&g_al[pix0 * C + c0]       = pl0.u;
            *(uint32_t*)&g_ah[(pix0 + 8) * C + c0] = ph1.u;
            *(uint32_t*)&g_al[(pix0 + 8) * C + c0] = pl1.u;
        }
    }
}

// ---------------------------------------------------------------------------
// out_conv: cp.async double-buffered pipeline. 18 stages = 9 taps x 2 ci-halves
// of 64. Per stage: A = W[tap][co][ci-half], B = act rows (x+dx-1)[ci-half].
// grid (H, B), 256 threads, 8 warps = 4(M co) x 2(N x).
// ---------------------------------------------------------------------------
__global__ void __launch_bounds__(256) out_conv_mma(const float* __restrict__ bo,
                                                    float* __restrict__ out) {
    extern __shared__ char smem[];
    uint32_t sb = smem_u32(smem);
    const int tid = threadIdx.x;
    const int wid = tid >> 5, lane = tid & 31;
    const int y = blockIdx.x, b = blockIdx.y;
    const int wm = wid & 3;
    const int wn = wid >> 2;

    float acc[2][8][4];
#pragma unroll
    for (int mt = 0; mt < 2; mt++)
#pragma unroll
        for (int nt = 0; nt < 8; nt++)
#pragma unroll
            for (int j = 0; j < 4; j++) acc[mt][nt][j] = 0.0f;

    // stage issue: t in [0,18), buffer bufsel
    auto issue = [&](int t, int bufsel) {
        int tap = t >> 1, kh = t & 1;
        int dy = tap / 3, dx = tap % 3;
        int yy = y + dy - 1;
        bool yok = (unsigned)yy < (unsigned)H;
        int yc = yok ? yy : 0;
        uint32_t bufo = sb + bufsel * OC_BUF;
#pragma unroll
        for (int l = 0; l < 16; l++) {
            int i = tid + 256 * l;              // 0..4095
            int region = i >> 10, idx = i & 1023;
            int row = idx >> 3, g = idx & 7;
            uint32_t daddr = bufo + region * OC_TILE + (uint32_t)row * LDT_S + g * 16;
            if (region < 2) {
                const __nv_bfloat16* src =
                    (region == 0 ? g_wh : g_wl) + (size_t)tap * (C * C) + row * C + kh * 64 + g * 8;
                cp16(daddr, src, true);
            } else {
                int xx = row + dx - 1;
                bool ok = yok && (unsigned)xx < (unsigned)W;
                int xc = ok ? xx : 0;
                const __nv_bfloat16* src =
                    (region == 2 ? g_ah : g_al)
                    + ((size_t)b * HW + yc * W + xc) * C + kh * 64 + g * 8;
                cp16(daddr, src, ok);
            }
        }
        CP_COMMIT();
    };

    issue(0, 0);
    issue(1, 1);

    for (int t = 0; t < 18; t++) {
        if (t < 17) asm volatile("cp.async.wait_group 1;" ::: "memory");
        else        asm volatile("cp.async.wait_group 0;" ::: "memory");
        __syncthreads();

        uint32_t bufo = sb + (t & 1) * OC_BUF;
#pragma unroll
        for (int ks = 0; ks < 4; ks++) {
            uint32_t ah[2][4], al[2][4], bh[4][4], bl[4][4];
#pragma unroll
            for (int mt = 0; mt < 2; mt++) {
                uint32_t addr = bufo
                    + (uint32_t)(wm * 32 + mt * 16 + (lane & 15)) * LDT_S
                    + (uint32_t)(ks * 16 + (lane >> 4) * 8) * 2;
                LDSM4(ah[mt], addr);
                LDSM4(al[mt], addr + OC_TILE);
            }
#pragma unroll
            for (int np = 0; np < 4; np++) {
                int n = wn * 64 + np * 16 + (lane & 7) + ((lane >> 4) & 1) * 8;
                int ko = ks * 16 + ((lane >> 3) & 1) * 8;
                uint32_t addr = bufo + 2 * OC_TILE + (uint32_t)n * LDT_S + (uint32_t)ko * 2;
                LDSM4(bh[np], addr);
                LDSM4(bl[np], addr + OC_TILE);
            }
#pragma unroll
            for (int mt = 0; mt < 2; mt++) {
#pragma unroll
                for (int nt = 0; nt < 8; nt++) {
                    int np = nt >> 1, hf = (nt & 1) * 2;
                    MMA_BF16(acc[mt][nt], ah[mt], bh[np][hf], bh[np][hf + 1]);
                    MMA_BF16(acc[mt][nt], ah[mt], bl[np][hf], bl[np][hf + 1]);
                    MMA_BF16(acc[mt][nt], al[mt], bh[np][hf], bh[np][hf + 1]);
                }
            }
        }
        __syncthreads();
        if (t + 2 < 18) issue(t + 2, t & 1);
    }

#pragma unroll
    for (int mt = 0; mt < 2; mt++) {
        int r0 = wm * 32 + mt * 16 + (lane >> 2);
        float bias0 = __ldg(bo + r0);
        float bias1 = __ldg(bo + r0 + 8);
        float* o0 = out + (size_t)(b * C + r0) * HW + (size_t)y * W;
        float* o1 = o0 + (size_t)8 * HW;
#pragma unroll
        for (int nt = 0; nt < 8; nt++) {
            int xc = wn * 64 + nt * 8 + (lane & 3) * 2;
            *(float2*)&o0[xc] = make_float2(acc[mt][nt][0] + bias0, acc[mt][nt][1] + bias0);
            *(float2*)&o1[xc] = make_float2(acc[mt][nt][2] + bias1, acc[mt][nt][3] + bias1);
        }
    }
}

// ---------------------------------------------------------------------------
extern "C" void kernel_launch(void* const* d_in, const int* in_sizes, int n_in,
                              void* d_out, int out_size) {
    const float* x  = (const float*)d_in[0];
    const float* wq = (const float*)d_in[1];
    const float* bq = (const float*)d_in[2];
    const float* wk = (const float*)d_in[3];
    const float* bk = (const float*)d_in[4];
    const float* wv = (const float*)d_in[5];
    const float* bv = (const float*)d_in[6];
    const float* wo = (const float*)d_in[7];
    const float* bo = (const float*)d_in[8];
    float* out = (float*)d_out;

    cudaFuncSetAttribute(score_mma,    cudaFuncAttributeMaxDynamicSharedMemorySize, SMEM_SCORE);
    cudaFuncSetAttribute(pv_mma,       cudaFuncAttributeMaxDynamicSharedMemorySize, SMEM_PV);
    cudaFuncSetAttribute(out_conv_mma, cudaFuncAttributeMaxDynamicSharedMemorySize, SMEM_OC);

    prep_w<<<(C * C * 9 + 255) / 256, 256>>>(wo);
    qkv_dwconv<<<dim3(W / 64, H / 32, B * C), 256>>>(x, wq, bq, wk, bk, wv, bv);
    v_transpose<<<dim3(HW / 32, C / 32, B), dim3(32, 8)>>>();
    score_mma<<<dim3(4, B * NH), 256, SMEM_SCORE>>>();
    softmax_p<<<(B * NH * C) / 8, 256>>>();
    pv_mma<<<dim3(HW / NH / 128, B * NH), 256, SMEM_PV>>>();
    out_conv_mma<<<dim3(H, B), 256, SMEM_OC>>>(bo, out);
}

// round 15
// speedup vs baseline: 2.3048x; 1.0457x over previous
#include <cuda_runtime.h>
#include <cuda_bf16.h>
#include <cstdint>

// ---------------------------------------------------------------------------
// MultiheadChannelAttention — R13: cp.async double-buffering in score_mma
// (3 CTAs/SM) and 2-phase cp.async staging in pv_mma. Rest from R11 (700 µs).
// ---------------------------------------------------------------------------

namespace {
constexpr int B = 8, C = 128, H = 128, W = 128;
constexpr int HW = 16384;
constexpr int NH = 8;
constexpr int D = HW / NH;     // 2048
constexpr float SCALE = 1.0f / 128.0f;

// pv tiles: 272B rows (128 + 8 pad bf16)
constexpr int LDT_B = 272;
constexpr int TILE_B2 = 128 * LDT_B;        // 34816
constexpr int SA_H = 0;
constexpr int SA_L = TILE_B2;
constexpr int SB_H = 2 * TILE_B2;
constexpr int SB_L = 3 * TILE_B2;
constexpr int SMEM_PV = 4 * TILE_B2;        // 139264

// score tiles: 144B rows (64 bf16 + 8 pad), 64 rows each; double buffered
constexpr int LDT_S = 144;
constexpr int SCT = 64 * LDT_S;             // 9216 per tile
constexpr int SCB = 4 * SCT;                // 36864 per buffer
constexpr int SMEM_SCORE = 2 * SCB;         // 73728

// out_conv pipeline: per-buffer 4 tiles of 128 rows x 144B
constexpr int OC_TILE = 128 * LDT_S;        // 18432
constexpr int OC_BUF = 4 * OC_TILE;         // 73728
constexpr int SMEM_OC = 2 * OC_BUF;         // 147456
}

typedef unsigned long long u64;

// Scratch (device globals: no allocation allowed)
__device__ __nv_bfloat16 g_qh[(size_t)B * C * HW];
__device__ __nv_bfloat16 g_ql[(size_t)B * C * HW];
__device__ __nv_bfloat16 g_kh[(size_t)B * C * HW];
__device__ __nv_bfloat16 g_kl[(size_t)B * C * HW];
__device__ float g_v[(size_t)B * C * HW];
__device__ __nv_bfloat16 g_vth[(size_t)B * HW * C];  // V^T [b][pix][c] hi
__device__ __nv_bfloat16 g_vtl[(size_t)B * HW * C];
__device__ float g_s[B * NH * C * C];                // scores (fp32)
__device__ __nv_bfloat16 g_ph[B * NH * C * C];       // softmax probs split
__device__ __nv_bfloat16 g_pl[B * NH * C * C];
__device__ __nv_bfloat16 g_ah[(size_t)B * HW * C];   // attn out [b][pix][ci]
__device__ __nv_bfloat16 g_al[(size_t)B * HW * C];
__device__ __nv_bfloat16 g_wh[9 * C * C];            // wo split [tap][co][ci]
__device__ __nv_bfloat16 g_wl[9 * C * C];

// ---------------- helpers ---------------------------------------------------
__device__ __forceinline__ uint32_t smem_u32(const void* p) {
    uint32_t a;
    asm("{ .reg .u64 t; cvta.to.shared.u64 t, %1; cvt.u32.u64 %0, t; }" : "=r"(a) : "l"(p));
    return a;
}

__device__ __forceinline__ void cp16(uint32_t dst, const void* src, bool ok) {
    int sz = ok ? 16 : 0;
    asm volatile("cp.async.cg.shared.global [%0], [%1], 16, %2;"
                 :: "r"(dst), "l"(src), "r"(sz) : "memory");
}
#define CP_COMMIT() asm volatile("cp.async.commit_group;" ::: "memory")

#define LDSM4(r, addr)                                                          \
    asm volatile("ldmatrix.sync.aligned.m8n8.x4.shared.b16 {%0,%1,%2,%3}, [%4];" \
        : "=r"((r)[0]), "=r"((r)[1]), "=r"((r)[2]), "=r"((r)[3]) : "r"(addr))

#define MMA_BF16(d, a, b0, b1)                                                  \
    asm volatile("mma.sync.aligned.m16n8k16.row.col.f32.bf16.bf16.f32 "         \
        "{%0,%1,%2,%3}, {%4,%5,%6,%7}, {%8,%9}, {%0,%1,%2,%3};"                 \
        : "+f"((d)[0]), "+f"((d)[1]), "+f"((d)[2]), "+f"((d)[3])                \
        : "r"((a)[0]), "r"((a)[1]), "r"((a)[2]), "r"((a)[3]), "r"(b0), "r"(b1))

union Pack8 { uint4 u; __nv_bfloat16 h[8]; };
union Pack2 { uint32_t u; __nv_bfloat16 h[2]; };

// ---------------------------------------------------------------------------
// Split wo [co][ci][tap] -> g_wh/g_wl [tap][co][ci] (bf16 hi/lo)
// ---------------------------------------------------------------------------
__global__ void prep_w(const float* __restrict__ wo) {
    int i = blockIdx.x * 256 + threadIdx.x;
    if (i >= C * C * 9) return;
    int co = i / (C * 9);
    int rem = i % (C * 9);
    int ci = rem / 9;
    int tap = rem % 9;
    float w = wo[i];
    __nv_bfloat16 hi = __float2bfloat16(w);
    __nv_bfloat16 lo = __float2bfloat16(w - __bfloat162float(hi));
    int dst = tap * (C * C) + co * C + ci;
    g_wh[dst] = hi;
    g_wl[dst] = lo;
}

// ---------------------------------------------------------------------------
// Fused q/k/v depthwise 9x9 conv (pad 4). q/k split bf16, v fp32.
// ---------------------------------------------------------------------------
__global__ void __launch_bounds__(256) qkv_dwconv(
        const float* __restrict__ x,
        const float* __restrict__ wq, const float* __restrict__ bq,
        const float* __restrict__ wk, const float* __restrict__ bk,
        const float* __restrict__ wv, const float* __restrict__ bv) {
    __shared__ float tile[40][72];
    __shared__ float wsm[3][81];

    int bc = blockIdx.z;
    int b = bc >> 7, c = bc & 127;
    int x0 = blockIdx.x * 64, y0 = blockIdx.y * 32;
    int tid = threadIdx.x;
    int lane = tid & 7;
    int r = tid >> 3;

    if (tid < 243) {
        int c3 = tid / 81, t = tid % 81;
        const float* wsrc = (c3 == 0) ? wq : (c3 == 1) ? wk : wv;
        wsm[c3][t] = wsrc[c * 81 + t];
    }
    const float* xp = x + (size_t)(b * C + c) * HW;
    for (int i = tid; i < 40 * 72; i += 256) {
        int tr = i / 72, tc = i % 72;
        int gy = y0 - 4 + tr, gx = x0 - 4 + tc;
        float v = 0.0f;
        if ((unsigned)gy < (unsigned)H && (unsigned)gx < (unsigned)W)
            v = xp[gy * W + gx];
        tile[tr][tc] = v;
    }
    __syncthreads();

    float aq[8], ak[8], av[8];
    float biasq = bq[c], biask = bk[c], biasv = bv[c];
#pragma unroll
    for (int p = 0; p < 8; p++) { aq[p] = biasq; ak[p] = biask; av[p] = biasv; }

#pragma unroll
    for (int ky = 0; ky < 9; ky++) {
        float win[16];
        float4 u0 = *(const float4*)&tile[r + ky][lane * 8];
        float4 u1 = *(const float4*)&tile[r + ky][lane * 8 + 4];
        float4 u2 = *(const float4*)&tile[r + ky][lane * 8 + 8];
        float4 u3 = *(const float4*)&tile[r + ky][lane * 8 + 12];
        win[0] = u0.x; win[1] = u0.y; win[2] = u0.z; win[3] = u0.w;
        win[4] = u1.x; win[5] = u1.y; win[6] = u1.z; win[7] = u1.w;
        win[8] = u2.x; win[9] = u2.y; win[10] = u2.z; win[11] = u2.w;
        win[12] = u3.x; win[13] = u3.y; win[14] = u3.z; win[15] = u3.w;
#pragma unroll
        for (int kx = 0; kx < 9; kx++) {
            float w0 = wsm[0][ky * 9 + kx];
            float w1 = wsm[1][ky * 9 + kx];
            float w2 = wsm[2][ky * 9 + kx];
#pragma unroll
            for (int p = 0; p < 8; p++) {
                float vi = win[p + kx];
                aq[p] += vi * w0;
                ak[p] += vi * w1;
                av[p] += vi * w2;
            }
        }
    }

    size_t o = (size_t)(b * C + c) * HW + (size_t)(y0 + r) * W + x0 + lane * 8;
    Pack8 qh, ql, kh, kl;
#pragma unroll
    for (int p = 0; p < 8; p++) {
        __nv_bfloat16 h1 = __float2bfloat16(aq[p]);
        qh.h[p] = h1;
        ql.h[p] = __float2bfloat16(aq[p] - __bfloat162float(h1));
        __nv_bfloat16 h2 = __float2bfloat16(ak[p]);
        kh.h[p] = h2;
        kl.h[p] = __float2bfloat16(ak[p] - __bfloat162float(h2));
    }
    *(uint4*)&g_qh[o] = qh.u;
    *(uint4*)&g_ql[o] = ql.u;
    *(uint4*)&g_kh[o] = kh.u;
    *(uint4*)&g_kl[o] = kl.u;
    *(float4*)&g_v[o]     = make_float4(av[0], av[1], av[2], av[3]);
    *(float4*)&g_v[o + 4] = make_float4(av[4], av[5], av[6], av[7]);
}

// ---------------------------------------------------------------------------
// V^T: g_v [b][c][hw] fp32 -> g_vth/g_vtl [b][pix][c] split bf16.
// ---------------------------------------------------------------------------
__global__ void v_transpose() {
    __shared__ float sm[32][33];
    int p0 = blockIdx.x * 32, c0 = blockIdx.y * 32, b = blockIdx.z;
    int tx = threadIdx.x, ty = threadIdx.y;
    int tid = ty * 32 + tx;

#pragma unroll
    for (int i = 0; i < 4; i++) {
        int c = c0 + ty + i * 8;
        sm[ty + i * 8][tx] = g_v[(size_t)(b * C + c) * HW + p0 + tx];
    }
    __syncthreads();

#pragma unroll
    for (int l = 0; l < 2; l++) {
        int i = tid + 256 * l;
        int p = i >> 4, pr = i & 15;
        float a = sm[pr * 2][p];
        float b2 = sm[pr * 2 + 1][p];
        __nv_bfloat16 ha = __float2bfloat16(a);
        __nv_bfloat16 hb = __float2bfloat16(b2);
        Pack2 hi, lo;
        hi.h[0] = ha; hi.h[1] = hb;
        lo.h[0] = __float2bfloat16(a - __bfloat162float(ha));
        lo.h[1] = __float2bfloat16(b2 - __bfloat162float(hb));
        size_t base = ((size_t)b * HW + p0 + p) * C + c0 + pr * 2;
        *(uint32_t*)&g_vth[base] = hi.u;
        *(uint32_t*)&g_vtl[base] = lo.u;
    }
}

// ---------------------------------------------------------------------------
// score_mma: S = (Q K^T)*SCALE per (b,h); 64x64 tiles, grid (4, B*NH).
// cp.async double-buffered K-loop (32 chunks of 64). 2 buffers x 36.9KB ->
// 3 CTAs/SM. 8 warps = 2(M:32) x 4(N:16).
// ---------------------------------------------------------------------------
__global__ void __launch_bounds__(256) score_mma() {
    extern __shared__ char smem[];
    uint32_t sb = smem_u32(smem);
    const int tid = threadIdx.x;
    const int wid = tid >> 5, lane = tid & 31;
    const int bh = blockIdx.y;
    const int b = bh >> 3, h = bh & 7;
    const int quad = blockIdx.x;
    const int r0 = (quad >> 1) * 64, c0 = (quad & 1) * 64;
    const int wm = wid & 1;
    const int wn = wid >> 1;

    const uint4* qhp = (const uint4*)g_qh;
    const uint4* qlp = (const uint4*)g_ql;
    const uint4* khp = (const uint4*)g_kh;
    const uint4* klp = (const uint4*)g_kl;

    const size_t qb0 = ((size_t)(b * C + r0) * HW + h * D) >> 3;
    const size_t kb0 = ((size_t)(b * C + c0) * HW + h * D) >> 3;

    float acc[2][2][4];
#pragma unroll
    for (int mt = 0; mt < 2; mt++)
#pragma unroll
        for (int nt = 0; nt < 2; nt++)
#pragma unroll
            for (int j = 0; j < 4; j++) acc[mt][nt][j] = 0.0f;

    auto issue = [&](int chunk, int bufsel) {
        size_t qbase = qb0 + chunk * 8;   // 64 bf16 = 8 uint4
        size_t kbase = kb0 + chunk * 8;
        uint32_t bufo = sb + bufsel * SCB;
#pragma unroll
        for (int l = 0; l < 8; l++) {
            int i = tid + 256 * l;       // 0..2047
            int region = i >> 9, idx = i & 511;
            int row = idx >> 3, g = idx & 7;
            uint32_t dst = bufo + region * SCT + (uint32_t)row * LDT_S + g * 16;
            const uint4* src;
            if (region == 0)      src = qhp + qbase + (size_t)row * (HW / 8) + g;
            else if (region == 1) src = qlp + qbase + (size_t)row * (HW / 8) + g;
            else if (region == 2) src = khp + kbase + (size_t)row * (HW / 8) + g;
            else                  src = klp + kbase + (size_t)row * (HW / 8) + g;
            cp16(dst, src, true);
        }
        CP_COMMIT();
    };

    issue(0, 0);
    issue(1, 1);

    for (int t = 0; t < 32; t++) {
        if (t < 31) asm volatile("cp.async.wait_group 1;" ::: "memory");
        else        asm volatile("cp.async.wait_group 0;" ::: "memory");
        __syncthreads();

        uint32_t bufo = sb + (t & 1) * SCB;
#pragma unroll
        for (int ks = 0; ks < 4; ks++) {
            uint32_t ah[2][4], al[2][4], bh4[4], bl4[4];
#pragma unroll
            for (int mt = 0; mt < 2; mt++) {
                uint32_t addr = bufo
                    + (uint32_t)(wm * 32 + mt * 16 + (lane & 15)) * LDT_S
                    + (uint32_t)(ks * 16 + (lane >> 4) * 8) * 2;
                LDSM4(ah[mt], addr);
                LDSM4(al[mt], addr + SCT);
            }
            {
                int n = wn * 16 + (lane & 7) + ((lane >> 4) & 1) * 8;
                int ko = ks * 16 + ((lane >> 3) & 1) * 8;
                uint32_t addr = bufo + 2 * SCT + (uint32_t)n * LDT_S + (uint32_t)ko * 2;
                LDSM4(bh4, addr);
                LDSM4(bl4, addr + SCT);
            }
#pragma unroll
            for (int mt = 0; mt < 2; mt++) {
#pragma unroll
                for (int nt = 0; nt < 2; nt++) {
                    int hf = nt * 2;
                    MMA_BF16(acc[mt][nt], ah[mt], bh4[hf], bh4[hf + 1]);
                    MMA_BF16(acc[mt][nt], ah[mt], bl4[hf], bl4[hf + 1]);
                    MMA_BF16(acc[mt][nt], al[mt], bh4[hf], bh4[hf + 1]);
                }
            }
        }
        __syncthreads();
        if (t + 2 < 32) issue(t + 2, t & 1);
    }

#pragma unroll
    for (int mt = 0; mt < 2; mt++) {
        int r = r0 + wm * 32 + mt * 16 + (lane >> 2);
#pragma unroll
        for (int nt = 0; nt < 2; nt++) {
            int cc = c0 + wn * 16 + nt * 8 + (lane & 3) * 2;
            *(float2*)&g_s[((size_t)bh * C + r) * C + cc] =
                make_float2(acc[mt][nt][0] * SCALE, acc[mt][nt][1] * SCALE);
            *(float2*)&g_s[((size_t)bh * C + r + 8) * C + cc] =
                make_float2(acc[mt][nt][2] * SCALE, acc[mt][nt][3] * SCALE);
        }
    }
}

// ---------------------------------------------------------------------------
// Row softmax over g_s; writes split bf16 P. One warp per row.
// ---------------------------------------------------------------------------
__global__ void softmax_p() {
    int gw = (blockIdx.x * blockDim.x + threadIdx.x) >> 5;
    int lane = threadIdx.x & 31;
    if (gw >= B * NH * C) return;
    float4 v = *(const float4*)&g_s[(size_t)gw * C + lane * 4];
    float m = fmaxf(fmaxf(v.x, v.y), fmaxf(v.z, v.w));
#pragma unroll
    for (int o = 16; o > 0; o >>= 1)
        m = fmaxf(m, __shfl_xor_sync(0xffffffffu, m, o));
    v.x = __expf(v.x - m);
    v.y = __expf(v.y - m);
    v.z = __expf(v.z - m);
    v.w = __expf(v.w - m);
    float s = v.x + v.y + v.z + v.w;
#pragma unroll
    for (int o = 16; o > 0; o >>= 1)
        s += __shfl_xor_sync(0xffffffffu, s, o);
    float inv = 1.0f / s;
    float p[4] = {v.x * inv, v.y * inv, v.z * inv, v.w * inv};

    Pack2 h0, h1, l0, l1;
#pragma unroll
    for (int j = 0; j < 4; j++) {
        __nv_bfloat16 hi = __float2bfloat16(p[j]);
        __nv_bfloat16 lo = __float2bfloat16(p[j] - __bfloat162float(hi));
        if (j < 2) { h0.h[j] = hi; l0.h[j] = lo; }
        else       { h1.h[j - 2] = hi; l1.h[j - 2] = lo; }
    }
    size_t base = (size_t)gw * C + lane * 4;
    *(uint32_t*)&g_ph[base]     = h0.u;
    *(uint32_t*)&g_ph[base + 2] = h1.u;
    *(uint32_t*)&g_pl[base]     = l0.u;
    *(uint32_t*)&g_pl[base + 2] = l1.u;
}

// ---------------------------------------------------------------------------
// pv_mma: out[pix][c] = sum_e V^T[pix][e] * P[c][e]; cp.async 2-phase staging
// (K halves of 64), mma on half 0 overlaps copy of half 1. grid (16, B*NH).
// ---------------------------------------------------------------------------
__global__ void __launch_bounds__(256) pv_mma() {
    extern __shared__ char smem[];
    uint32_t sb = smem_u32(smem);
    const int tid = threadIdx.x;
    const int wid = tid >> 5, lane = tid & 31;
    const int bh = blockIdx.y;
    const int b = bh >> 3, h = bh & 7;
    const int dt = blockIdx.x * 128;
    const int wm = wid & 3;
    const int wn = wid >> 2;

    const uint4* vhp = (const uint4*)g_vth;
    const uint4* vlp = (const uint4*)g_vtl;
    const uint4* php = (const uint4*)g_ph;
    const uint4* plp = (const uint4*)g_pl;

    size_t abase = ((size_t)b * HW + h * D + dt) * C >> 3;
    size_t bbase = (size_t)bh * C * C >> 3;

    auto issue_half = [&](int kh) {
#pragma unroll
        for (int l = 0; l < 16; l++) {
            int i = tid + 256 * l;           // 0..4095
            int region = i >> 10, idx = i & 1023;
            int row = idx >> 3, g = idx & 7;
            uint32_t dst = sb + region * TILE_B2 + (uint32_t)row * LDT_B + kh * 128 + g * 16;
            size_t gi = (size_t)row * 16 + kh * 8 + g;
            const uint4* src;
            if (region == 0)      src = vhp + abase + gi;
            else if (region == 1) src = vlp + abase + gi;
            else if (region == 2) src = php + bbase + gi;
            else                  src = plp + bbase + gi;
            cp16(dst, src, true);
        }
        CP_COMMIT();
    };

    issue_half(0);
    issue_half(1);

    float acc[2][8][4];
#pragma unroll
    for (int mt = 0; mt < 2; mt++)
#pragma unroll
        for (int nt = 0; nt < 8; nt++)
#pragma unroll
            for (int j = 0; j < 4; j++) acc[mt][nt][j] = 0.0f;

#pragma unroll
    for (int half = 0; half < 2; half++) {
        if (half == 0) asm volatile("cp.async.wait_group 1;" ::: "memory");
        else           asm volatile("cp.async.wait_group 0;" ::: "memory");
        __syncthreads();

#pragma unroll
        for (int kss = 0; kss < 4; kss++) {
            int ks = half * 4 + kss;
            uint32_t ah[2][4], al[2][4], bh4[4][4], bl4[4][4];
#pragma unroll
            for (int mt = 0; mt < 2; mt++) {
                uint32_t addr = sb + SA_H
                    + (uint32_t)(wm * 32 + mt * 16 + (lane & 15)) * LDT_B
                    + (uint32_t)(ks * 16 + (lane >> 4) * 8) * 2;
                LDSM4(ah[mt], addr);
                LDSM4(al[mt], addr + TILE_B2);
            }
#pragma unroll
            for (int np = 0; np < 4; np++) {
                int n = wn * 64 + np * 16 + (lane & 7) + ((lane >> 4) & 1) * 8;
                int ko = ks * 16 + ((lane >> 3) & 1) * 8;
                uint32_t addr = sb + SB_H + (uint32_t)n * LDT_B + (uint32_t)ko * 2;
                LDSM4(bh4[np], addr);
                LDSM4(bl4[np], addr + TILE_B2);
            }
#pragma unroll
            for (int mt = 0; mt < 2; mt++) {
#pragma unroll
                for (int nt = 0; nt < 8; nt++) {
                    int np = nt >> 1, hf = (nt & 1) * 2;
                    MMA_BF16(acc[mt][nt], ah[mt], bh4[np][hf], bh4[np][hf + 1]);
                    MMA_BF16(acc[mt][nt], ah[mt], bl4[np][hf], bl4[np][hf + 1]);
                    MMA_BF16(acc[mt][nt], al[mt], bh4[np][hf], bh4[np][hf + 1]);
                }
            }
        }
    }

#pragma unroll
    for (int mt = 0; mt < 2; mt++) {
        size_t pix0 = (size_t)b * HW + h * D + dt + wm * 32 + mt * 16 + (lane >> 2);
#pragma unroll
        for (int nt = 0; nt < 8; nt++) {
            int c0 = wn * 64 + nt * 8 + (lane & 3) * 2;
            float a0 = acc[mt][nt][0], a1 = acc[mt][nt][1];
            float a2 = acc[mt][nt][2], a3 = acc[mt][nt][3];
            __nv_bfloat16 h0 = __float2bfloat16(a0);
            __nv_bfloat16 h1 = __float2bfloat16(a1);
            __nv_bfloat16 h2 = __float2bfloat16(a2);
            __nv_bfloat16 h3 = __float2bfloat16(a3);
            Pack2 ph0, pl0, ph1, pl1;
            ph0.h[0] = h0; ph0.h[1] = h1;
            pl0.h[0] = __float2bfloat16(a0 - __bfloat162float(h0));
            pl0.h[1] = __float2bfloat16(a1 - __bfloat162float(h1));
            ph1.h[0] = h2; ph1.h[1] = h3;
            pl1.h[0] = __float2bfloat16(a2 - __bfloat162float(h2));
            pl1.h[1] = __float2bfloat16(a3 - __bfloat162float(h3));
            *(uint32_t*)&g_ah[pix0 * C + c0]       = ph0.u;
            *(uint32_t*)&g_al[pix0 * C + c0]       = pl0.u;
            *(uint32_t*)&g_ah[(pix0 + 8) * C + c0] = ph1.u;
            *(uint32_t*)&g_al[(pix0 + 8) * C + c0] = pl1.u;
        }
    }
}

// ---------------------------------------------------------------------------
// out_conv: cp.async double-buffered pipeline (unchanged from R11).
// ---------------------------------------------------------------------------
__global__ void __launch_bounds__(256) out_conv_mma(const float* __restrict__ bo,
                                                    float* __restrict__ out) {
    extern __shared__ char smem[];
    uint32_t sb = smem_u32(smem);
    const int tid = threadIdx.x;
    const int wid = tid >> 5, lane = tid & 31;
    const int y = blockIdx.x, b = blockIdx.y;
    const int wm = wid & 3;
    const int wn = wid >> 2;

    float acc[2][8][4];
#pragma unroll
    for (int mt = 0; mt < 2; mt++)
#pragma unroll
        for (int nt = 0; nt < 8; nt++)
#pragma unroll
            for (int j = 0; j < 4; j++) acc[mt][nt][j] = 0.0f;

    auto issue = [&](int t, int bufsel) {
        int tap = t >> 1, kh = t & 1;
        int dy = tap / 3, dx = tap % 3;
        int yy = y + dy - 1;
        bool yok = (unsigned)yy < (unsigned)H;
        int yc = yok ? yy : 0;
        uint32_t bufo = sb + bufsel * OC_BUF;
#pragma unroll
        for (int l = 0; l < 16; l++) {
            int i = tid + 256 * l;
            int region = i >> 10, idx = i & 1023;
            int row = idx >> 3, g = idx & 7;
            uint32_t daddr = bufo + region * OC_TILE + (uint32_t)row * LDT_S + g * 16;
            if (region < 2) {
                const __nv_bfloat16* src =
                    (region == 0 ? g_wh : g_wl) + (size_t)tap * (C * C) + row * C + kh * 64 + g * 8;
                cp16(daddr, src, true);
            } else {
                int xx = row + dx - 1;
                bool ok = yok && (unsigned)xx < (unsigned)W;
                int xc = ok ? xx : 0;
                const __nv_bfloat16* src =
                    (region == 2 ? g_ah : g_al)
                    + ((size_t)b * HW + yc * W + xc) * C + kh * 64 + g * 8;
                cp16(daddr, src, ok);
            }
        }
        CP_COMMIT();
    };

    issue(0, 0);
    issue(1, 1);

    for (int t = 0; t < 18; t++) {
        if (t < 17) asm volatile("cp.async.wait_group 1;" ::: "memory");
        else        asm volatile("cp.async.wait_group 0;" ::: "memory");
        __syncthreads();

        uint32_t bufo = sb + (t & 1) * OC_BUF;
#pragma unroll
        for (int ks = 0; ks < 4; ks++) {
            uint32_t ah[2][4], al[2][4], bh4[4][4], bl4[4][4];
#pragma unroll
            for (int mt = 0; mt < 2; mt++) {
                uint32_t addr = bufo
                    + (uint32_t)(wm * 32 + mt * 16 + (lane & 15)) * LDT_S
                    + (uint32_t)(ks * 16 + (lane >> 4) * 8) * 2;
                LDSM4(ah[mt], addr);
                LDSM4(al[mt], addr + OC_TILE);
            }
#pragma unroll
            for (int np = 0; np < 4; np++) {
                int n = wn * 64 + np * 16 + (lane & 7) + ((lane >> 4) & 1) * 8;
                int ko = ks * 16 + ((lane >> 3) & 1) * 8;
                uint32_t addr = bufo + 2 * OC_TILE + (uint32_t)n * LDT_S + (uint32_t)ko * 2;
                LDSM4(bh4[np], addr);
                LDSM4(bl4[np], addr + OC_TILE);
            }
#pragma unroll
            for (int mt = 0; mt < 2; mt++) {
#pragma unroll
                for (int nt = 0; nt < 8; nt++) {
                    int np = nt >> 1, hf = (nt & 1) * 2;
                    MMA_BF16(acc[mt][nt], ah[mt], bh4[np][hf], bh4[np][hf + 1]);
                    MMA_BF16(acc[mt][nt], ah[mt], bl4[np][hf], bl4[np][hf + 1]);
                    MMA_BF16(acc[mt][nt], al[mt], bh4[np][hf], bh4[np][hf + 1]);
                }
            }
        }
        __syncthreads();
        if (t + 2 < 18) issue(t + 2, t & 1);
    }

#pragma unroll
    for (int mt = 0; mt < 2; mt++) {
        int r0 = wm * 32 + mt * 16 + (lane >> 2);
        float bias0 = __ldg(bo + r0);
        float bias1 = __ldg(bo + r0 + 8);
        float* o0 = out + (size_t)(b * C + r0) * HW + (size_t)y * W;
        float* o1 = o0 + (size_t)8 * HW;
#pragma unroll
        for (int nt = 0; nt < 8; nt++) {
            int xc = wn * 64 + nt * 8 + (lane & 3) * 2;
            *(float2*)&o0[xc] = make_float2(acc[mt][nt][0] + bias0, acc[mt][nt][1] + bias0);
            *(float2*)&o1[xc] = make_float2(acc[mt][nt][2] + bias1, acc[mt][nt][3] + bias1);
        }
    }
}

// ---------------------------------------------------------------------------
extern "C" void kernel_launch(void* const* d_in, const int* in_sizes, int n_in,
                              void* d_out, int out_size) {
    const float* x  = (const float*)d_in[0];
    const float* wq = (const float*)d_in[1];
    const float* bq = (const float*)d_in[2];
    const float* wk = (const float*)d_in[3];
    const float* bk = (const float*)d_in[4];
    const float* wv = (const float*)d_in[5];
    const float* bv = (const float*)d_in[6];
    const float* wo = (const float*)d_in[7];
    const float* bo = (const float*)d_in[8];
    float* out = (float*)d_out;

    cudaFuncSetAttribute(score_mma,    cudaFuncAttributeMaxDynamicSharedMemorySize, SMEM_SCORE);
    cudaFuncSetAttribute(pv_mma,       cudaFuncAttributeMaxDynamicSharedMemorySize, SMEM_PV);
    cudaFuncSetAttribute(out_conv_mma, cudaFuncAttributeMaxDynamicSharedMemorySize, SMEM_OC);

    prep_w<<<(C * C * 9 + 255) / 256, 256>>>(wo);
    qkv_dwconv<<<dim3(W / 64, H / 32, B * C), 256>>>(x, wq, bq, wk, bk, wv, bv);
    v_transpose<<<dim3(HW / 32, C / 32, B), dim3(32, 8)>>>();
    score_mma<<<dim3(4, B * NH), 256, SMEM_SCORE>>>();
    softmax_p<<<(B * NH * C) / 8, 256>>>();
    pv_mma<<<dim3(HW / NH / 128, B * NH), 256, SMEM_PV>>>();
    out_conv_mma<<<dim3(H, B), 256, SMEM_OC>>>(bo, out);
}